// round 2
// baseline (speedup 1.0000x reference)
#include <cuda_runtime.h>
#include <math.h>

// Problem dims (fixed by setup_inputs)
#define B_   256
#define D_   256
#define D1   1024
#define D2   512
#define D3   256
#define NDIST (D1 + D2 + D3)   // 1792
#define KSEL 10

typedef unsigned long long ULL;

// ---------------- scratch (device globals; no cudaMalloc allowed) ----------
__device__ float g_z1[B_ * D1];
__device__ float g_h1[B_ * D1];
__device__ float g_m1[B_ * D1];
__device__ float g_z2[B_ * D2];
__device__ float g_h2[B_ * D2];
__device__ float g_m2[B_ * D2];
__device__ float g_z3[B_ * D3];
__device__ float g_V2[(size_t)B_ * D2 * D_];   // 128 MB
__device__ float g_V3[(size_t)B_ * D3 * D_];   //  64 MB
__device__ float g_dists[B_ * NDIST];
__device__ float g_partial[B_];

// ---------------- packed f32x2 helpers -------------------------------------
__device__ __forceinline__ ULL dup2(float x) {
    ULL r;
    asm("mov.b64 %0, {%1, %1};" : "=l"(r) : "f"(x));
    return r;
}
__device__ __forceinline__ void fma2(ULL& c, ULL a, ULL b) {
    asm("fma.rn.f32x2 %0, %1, %2, %0;" : "+l"(c) : "l"(a), "l"(b));
}

// ---------------- small forward-pass GEMM: Z = X @ W^T + bias --------------
// X [M,K] row-major, W [N,K] row-major. Optional relu H and 0/1 mask out.
__global__ __launch_bounds__(256) void zgemm_nt(
    const float* __restrict__ X, const float* __restrict__ W,
    const float* __restrict__ bias, int M, int N, int K,
    float* __restrict__ Z, float* __restrict__ H, float* __restrict__ Mk)
{
    const int BM = 64, BN = 64, BK = 16;
    __shared__ __align__(16) float Xs[BK][BM];
    __shared__ __align__(16) float Ws[BK][BN];

    int m0 = blockIdx.y * BM, n0 = blockIdx.x * BN;
    int tid = threadIdx.x;
    int tx = tid & 15, ty = tid >> 4;
    int lrow = tid >> 2, lcol = (tid & 3) * 4;   // 64 rows x 16 cols tile load

    float acc[4][4];
#pragma unroll
    for (int i = 0; i < 4; i++)
#pragma unroll
        for (int j = 0; j < 4; j++) acc[i][j] = 0.f;

    for (int k0 = 0; k0 < K; k0 += BK) {
        float4 xa = *(const float4*)(X + (size_t)(m0 + lrow) * K + k0 + lcol);
        float4 wa = *(const float4*)(W + (size_t)(n0 + lrow) * K + k0 + lcol);
        __syncthreads();
        Xs[lcol + 0][lrow] = xa.x; Xs[lcol + 1][lrow] = xa.y;
        Xs[lcol + 2][lrow] = xa.z; Xs[lcol + 3][lrow] = xa.w;
        Ws[lcol + 0][lrow] = wa.x; Ws[lcol + 1][lrow] = wa.y;
        Ws[lcol + 2][lrow] = wa.z; Ws[lcol + 3][lrow] = wa.w;
        __syncthreads();
#pragma unroll
        for (int k = 0; k < BK; k++) {
            float4 av = *(float4*)&Xs[k][ty * 4];
            float4 wv = *(float4*)&Ws[k][tx * 4];
            float a[4] = {av.x, av.y, av.z, av.w};
            float w[4] = {wv.x, wv.y, wv.z, wv.w};
#pragma unroll
            for (int i = 0; i < 4; i++)
#pragma unroll
                for (int j = 0; j < 4; j++) acc[i][j] += a[i] * w[j];
        }
    }

#pragma unroll
    for (int i = 0; i < 4; i++) {
        int m = m0 + ty * 4 + i;
#pragma unroll
        for (int j = 0; j < 4; j++) {
            int n = n0 + tx * 4 + j;
            float zv = acc[i][j] + bias[n];
            size_t o = (size_t)m * N + n;
            Z[o] = zv;
            if (H)  H[o]  = zv > 0.f ? zv : 0.f;
            if (Mk) Mk[o] = zv > 0.f ? 1.f : 0.f;
        }
    }
}

// ---------------- big batched masked GEMM ----------------------------------
// C[b] = (A ∘ mask[b]) @ Bm[b]
//   A    [M,K] row-major (shared across batch)
//   mask [B_,K] (0/1 floats), scales A columns
//   Bm   [K,N] row-major, per-batch base = Bm + b*bstride (bstride=0 → shared)
//   C    [B_,M,N]
// Tile: BM=128, BN=256, BK=8; 256 threads; 8x16 per-thread microtile via
// packed fma.rn.f32x2 (two N columns per accumulator).
__global__ __launch_bounds__(256, 1) void masked_gemm(
    const float* __restrict__ A, const float* __restrict__ mask,
    const float* __restrict__ Bm, size_t bstride,
    float* __restrict__ C, int M, int N, int K)
{
    const int BM = 128, BN = 256, BK = 8;
    __shared__ __align__(16) float As[2][BK][132];   // padded rows: STS conflict-free
    __shared__ __align__(16) float Bs[2][BK][BN];

    int b  = blockIdx.z;
    int m0 = blockIdx.y * BM;
    int n0 = blockIdx.x * BN;

    const float* mb = mask + (size_t)b * K;
    const float* Bb = Bm + (size_t)b * bstride;

    int tid = threadIdx.x;
    int tx = tid & 15, ty = tid >> 4;
    int arow = tid >> 1, acol = (tid & 1) * 4;       // A tile: 128 rows x 8 cols
    int brow = tid >> 6, bcol = (tid & 63) * 4;      // B tile: rows brow, brow+4

    ULL acc[8][8];
#pragma unroll
    for (int i = 0; i < 8; i++)
#pragma unroll
        for (int j = 0; j < 8; j++) acc[i][j] = 0ull;

    // preload k0 = 0
    {
        float4 a  = *(const float4*)(A  + (size_t)(m0 + arow) * K + acol);
        float4 mk = *(const float4*)(mb + acol);
        a.x *= mk.x; a.y *= mk.y; a.z *= mk.z; a.w *= mk.w;
        float4 b0 = *(const float4*)(Bb + (size_t)(brow)     * N + n0 + bcol);
        float4 b1 = *(const float4*)(Bb + (size_t)(brow + 4) * N + n0 + bcol);
        As[0][acol + 0][arow] = a.x; As[0][acol + 1][arow] = a.y;
        As[0][acol + 2][arow] = a.z; As[0][acol + 3][arow] = a.w;
        *(float4*)&Bs[0][brow][bcol]     = b0;
        *(float4*)&Bs[0][brow + 4][bcol] = b1;
    }
    __syncthreads();

    int cur = 0;
    for (int k0 = 0; k0 < K; k0 += BK) {
        int nk = k0 + BK;
        float4 na, nmk, nb0, nb1;
        if (nk < K) {
            na  = *(const float4*)(A  + (size_t)(m0 + arow) * K + nk + acol);
            nmk = *(const float4*)(mb + nk + acol);
            nb0 = *(const float4*)(Bb + (size_t)(nk + brow)     * N + n0 + bcol);
            nb1 = *(const float4*)(Bb + (size_t)(nk + brow + 4) * N + n0 + bcol);
        }
#pragma unroll
        for (int k = 0; k < BK; k++) {
            float4 a0 = *(float4*)&As[cur][k][ty * 8];
            float4 a1 = *(float4*)&As[cur][k][ty * 8 + 4];
            ULL bv[8];
#pragma unroll
            for (int jj = 0; jj < 4; jj++) {
                // thread's N-columns: tx*4 + jj*64 (strided → low bank conflicts)
                ulonglong2 t = *(ulonglong2*)&Bs[cur][k][tx * 4 + jj * 64];
                bv[2 * jj]     = t.x;
                bv[2 * jj + 1] = t.y;
            }
            float av[8] = {a0.x, a0.y, a0.z, a0.w, a1.x, a1.y, a1.z, a1.w};
#pragma unroll
            for (int i = 0; i < 8; i++) {
                ULL ad = dup2(av[i]);
#pragma unroll
                for (int j = 0; j < 8; j++) fma2(acc[i][j], ad, bv[j]);
            }
        }
        if (nk < K) {
            na.x *= nmk.x; na.y *= nmk.y; na.z *= nmk.z; na.w *= nmk.w;
            int nxt = cur ^ 1;
            As[nxt][acol + 0][arow] = na.x; As[nxt][acol + 1][arow] = na.y;
            As[nxt][acol + 2][arow] = na.z; As[nxt][acol + 3][arow] = na.w;
            *(float4*)&Bs[nxt][brow][bcol]     = nb0;
            *(float4*)&Bs[nxt][brow + 4][bcol] = nb1;
            __syncthreads();
            cur = nxt;
        }
    }

    float* Cb = C + (size_t)b * M * N;
#pragma unroll
    for (int i = 0; i < 8; i++) {
        size_t roff = (size_t)(m0 + ty * 8 + i) * N + n0;
#pragma unroll
        for (int jj = 0; jj < 4; jj++) {
            ulonglong2 v;
            v.x = acc[i][2 * jj];
            v.y = acc[i][2 * jj + 1];
            *(ulonglong2*)(Cb + roff + tx * 4 + jj * 64) = v;
        }
    }
}

// ---------------- distances: dist = |z| / ||V_row|| (row length = 256) -----
// V row base = V + b*vbs + r*256  (vbs=0 → shared across batch, e.g. W1)
__global__ void dist_kernel(const float* __restrict__ z, int zc,
                            const float* __restrict__ V, size_t vbs, int off)
{
    int warp = (blockIdx.x * blockDim.x + threadIdx.x) >> 5;
    int lane = threadIdx.x & 31;
    int total = B_ * zc;
    if (warp >= total) return;
    int b = warp / zc, r = warp % zc;
    const float4* vp = (const float4*)(V + (size_t)b * vbs + (size_t)r * 256);
    float4 v0 = vp[lane * 2];
    float4 v1 = vp[lane * 2 + 1];
    float s = v0.x * v0.x + v0.y * v0.y + v0.z * v0.z + v0.w * v0.w
            + v1.x * v1.x + v1.y * v1.y + v1.z * v1.z + v1.w * v1.w;
#pragma unroll
    for (int o = 16; o; o >>= 1) s += __shfl_xor_sync(0xffffffffu, s, o);
    if (lane == 0)
        g_dists[b * NDIST + off + r] = fabsf(z[(size_t)b * zc + r]) * rsqrtf(s);
}

// ---------------- per-batch smallest-k sum ----------------------------------
__global__ void topk_kernel()
{
    __shared__ float s[NDIST];
    __shared__ float rv[256];
    __shared__ int   ri[256];
    int b = blockIdx.x, t = threadIdx.x;
    for (int i = t; i < NDIST; i += 256) s[i] = g_dists[b * NDIST + i];
    __syncthreads();
    float tot = 0.f;
    for (int it = 0; it < KSEL; it++) {
        float best = 3.402823466e38f; int bi = NDIST;
        for (int i = t; i < NDIST; i += 256) {
            float v = s[i];
            if (v < best) { best = v; bi = i; }
        }
        rv[t] = best; ri[t] = bi;
        __syncthreads();
        for (int st = 128; st > 0; st >>= 1) {
            if (t < st) {
                if (rv[t + st] < rv[t] ||
                    (rv[t + st] == rv[t] && ri[t + st] < ri[t])) {
                    rv[t] = rv[t + st]; ri[t] = ri[t + st];
                }
            }
            __syncthreads();
        }
        if (t == 0) { tot += rv[0]; s[ri[0]] = 3.402823466e38f; }
        __syncthreads();
    }
    if (t == 0) g_partial[b] = tot;
}

__global__ void final_reduce(float* __restrict__ out)
{
    __shared__ float sh[256];
    int t = threadIdx.x;
    sh[t] = g_partial[t];
    __syncthreads();
    for (int st = 128; st > 0; st >>= 1) {
        if (t < st) sh[t] += sh[t + st];
        __syncthreads();
    }
    if (t == 0) out[0] = sh[0];
}

// ---------------- launch -----------------------------------------------------
extern "C" void kernel_launch(void* const* d_in, const int* in_sizes, int n_in,
                              void* d_out, int out_size)
{
    const float* x  = (const float*)d_in[0];
    const float* W1 = (const float*)d_in[1];
    const float* b1 = (const float*)d_in[2];
    const float* W2 = (const float*)d_in[3];
    const float* b2 = (const float*)d_in[4];
    const float* W3 = (const float*)d_in[5];
    const float* b3 = (const float*)d_in[6];
    float* out = (float*)d_out;

    float *z1p, *h1p, *m1p, *z2p, *h2p, *m2p, *z3p, *V2p, *V3p;
    cudaGetSymbolAddress((void**)&z1p, g_z1);
    cudaGetSymbolAddress((void**)&h1p, g_h1);
    cudaGetSymbolAddress((void**)&m1p, g_m1);
    cudaGetSymbolAddress((void**)&z2p, g_z2);
    cudaGetSymbolAddress((void**)&h2p, g_h2);
    cudaGetSymbolAddress((void**)&m2p, g_m2);
    cudaGetSymbolAddress((void**)&z3p, g_z3);
    cudaGetSymbolAddress((void**)&V2p, g_V2);
    cudaGetSymbolAddress((void**)&V3p, g_V3);

    // Forward pass (exact fp32 so masks match the reference)
    zgemm_nt<<<dim3(D1 / 64, B_ / 64), 256>>>(x,   W1, b1, B_, D1, D_,  z1p, h1p, m1p);
    zgemm_nt<<<dim3(D2 / 64, B_ / 64), 256>>>(h1p, W2, b2, B_, D2, D1, z2p, h2p, m2p);
    zgemm_nt<<<dim3(D3 / 64, B_ / 64), 256>>>(h2p, W3, b3, B_, D3, D2, z3p, (float*)0, (float*)0);

    // V2[b] = (W2 ∘ m1[b]) @ W1        [512 x 256] per batch
    masked_gemm<<<dim3(1, D2 / 128, B_), 256>>>(W2, m1p, W1, 0, V2p, D2, D_, D1);
    // V3[b] = (W3 ∘ m2[b]) @ V2[b]     [256 x 256] per batch
    masked_gemm<<<dim3(1, D3 / 128, B_), 256>>>(W3, m2p, V2p, (size_t)D2 * D_, V3p, D3, D_, D2);

    // distances
    {
        int rows1 = B_ * D1, rows2 = B_ * D2, rows3 = B_ * D3;
        dist_kernel<<<rows1 / 8, 256>>>(z1p, D1, W1, 0, 0);
        dist_kernel<<<rows2 / 8, 256>>>(z2p, D2, V2p, (size_t)D2 * D_, D1);
        dist_kernel<<<rows3 / 8, 256>>>(z3p, D3, V3p, (size_t)D3 * D_, D1 + D2);
    }

    // per-batch smallest-10 sums, then deterministic reduction
    topk_kernel<<<B_, 256>>>();
    final_reduce<<<1, 256>>>(out);
}

// round 4
// speedup vs baseline: 4.0132x; 4.0132x over previous
#include <cuda_runtime.h>
#include <cuda_bf16.h>
#include <math.h>
#include <stdint.h>

// Problem dims (fixed by setup_inputs)
#define B_   256
#define D_   256
#define D1   1024
#define D2   512
#define D3   256
#define NDIST (D1 + D2 + D3)   // 1792
#define KSEL 10

// ---------------- scratch (device globals; no cudaMalloc allowed) ----------
__device__ float g_z1[B_ * D1];
__device__ float g_h1[B_ * D1];
__device__ __nv_bfloat16 g_m1b[B_ * D1];
__device__ float g_z2[B_ * D2];
__device__ float g_h2[B_ * D2];
__device__ __nv_bfloat16 g_m2b[B_ * D2];
__device__ float g_z3[B_ * D3];
__device__ __nv_bfloat16 g_W2h[D2 * D1];
__device__ __nv_bfloat16 g_W3h[D3 * D2];
__device__ __nv_bfloat16 g_W1Th[D_ * D1];                 // W1^T [256,1024]
__device__ __nv_bfloat16 g_V2T[(size_t)B_ * D_ * D2];     // [B][256][512]
__device__ float g_invn1[D1];
__device__ float g_dists[B_ * NDIST];
__device__ float g_partial[B_];

// ---------------- PTX helpers ------------------------------------------------
__device__ __forceinline__ uint32_t smem_u32(const void* p) {
    uint32_t a;
    asm("{ .reg .u64 t; cvta.to.shared.u64 t, %1; cvt.u32.u64 %0, t; }"
        : "=r"(a) : "l"(p));
    return a;
}
__device__ __forceinline__ void cpasync16(uint32_t dst, const void* src) {
    asm volatile("cp.async.cg.shared.global [%0], [%1], 16;"
                 :: "r"(dst), "l"(src) : "memory");
}
__device__ __forceinline__ void ldm4(uint32_t r[4], uint32_t addr) {
    asm volatile("ldmatrix.sync.aligned.m8n8.x4.shared.b16 {%0,%1,%2,%3}, [%4];"
                 : "=r"(r[0]), "=r"(r[1]), "=r"(r[2]), "=r"(r[3]) : "r"(addr));
}
__device__ __forceinline__ void mma16816(float* c, const uint32_t a[4],
                                         uint32_t b0, uint32_t b1) {
    asm volatile(
        "mma.sync.aligned.m16n8k16.row.col.f32.bf16.bf16.f32 "
        "{%0,%1,%2,%3}, {%4,%5,%6,%7}, {%8,%9}, {%0,%1,%2,%3};"
        : "+f"(c[0]), "+f"(c[1]), "+f"(c[2]), "+f"(c[3])
        : "r"(a[0]), "r"(a[1]), "r"(a[2]), "r"(a[3]), "r"(b0), "r"(b1));
}

// ---------------- forward-pass GEMM: Z = X @ W^T + bias --------------------
__global__ __launch_bounds__(256) void zgemm_nt(
    const float* __restrict__ X, const float* __restrict__ W,
    const float* __restrict__ bias, int M, int N, int K,
    float* __restrict__ Z, float* __restrict__ H, __nv_bfloat16* __restrict__ Mk)
{
    const int BM = 64, BN = 64, BK = 16;
    __shared__ __align__(16) float Xs[BK][BM];
    __shared__ __align__(16) float Ws[BK][BN];

    int m0 = blockIdx.y * BM, n0 = blockIdx.x * BN;
    int tid = threadIdx.x;
    int tx = tid & 15, ty = tid >> 4;
    int lrow = tid >> 2, lcol = (tid & 3) * 4;

    float acc[4][4];
#pragma unroll
    for (int i = 0; i < 4; i++)
#pragma unroll
        for (int j = 0; j < 4; j++) acc[i][j] = 0.f;

    for (int k0 = 0; k0 < K; k0 += BK) {
        float4 xa = *(const float4*)(X + (size_t)(m0 + lrow) * K + k0 + lcol);
        float4 wa = *(const float4*)(W + (size_t)(n0 + lrow) * K + k0 + lcol);
        __syncthreads();
        Xs[lcol + 0][lrow] = xa.x; Xs[lcol + 1][lrow] = xa.y;
        Xs[lcol + 2][lrow] = xa.z; Xs[lcol + 3][lrow] = xa.w;
        Ws[lcol + 0][lrow] = wa.x; Ws[lcol + 1][lrow] = wa.y;
        Ws[lcol + 2][lrow] = wa.z; Ws[lcol + 3][lrow] = wa.w;
        __syncthreads();
#pragma unroll
        for (int k = 0; k < BK; k++) {
            float4 av = *(float4*)&Xs[k][ty * 4];
            float4 wv = *(float4*)&Ws[k][tx * 4];
            float a[4] = {av.x, av.y, av.z, av.w};
            float w[4] = {wv.x, wv.y, wv.z, wv.w};
#pragma unroll
            for (int i = 0; i < 4; i++)
#pragma unroll
                for (int j = 0; j < 4; j++) acc[i][j] += a[i] * w[j];
        }
    }

#pragma unroll
    for (int i = 0; i < 4; i++) {
        int m = m0 + ty * 4 + i;
#pragma unroll
        for (int j = 0; j < 4; j++) {
            int n = n0 + tx * 4 + j;
            float zv = acc[i][j] + bias[n];
            size_t o = (size_t)m * N + n;
            Z[o] = zv;
            if (H)  H[o]  = zv > 0.f ? zv : 0.f;
            if (Mk) Mk[o] = __float2bfloat16(zv > 0.f ? 1.f : 0.f);
        }
    }
}

// ---------------- precompute kernels ----------------------------------------
__global__ void to_bf16(const float* __restrict__ s, __nv_bfloat16* __restrict__ d, int n)
{
    int i = blockIdx.x * 256 + threadIdx.x;
    if (i < n) d[i] = __float2bfloat16(s[i]);
}

// transpose W1 [1024,256] -> W1T [256,1024] bf16
__global__ void w1t_cast(const float* __restrict__ W1)
{
    int i = blockIdx.x * 256 + threadIdx.x;
    int n = i >> 10, k = i & 1023;
    g_W1Th[i] = __float2bfloat16(W1[(size_t)k * D_ + n]);
}

__global__ void w1norm(const float* __restrict__ W1)
{
    int warp = (blockIdx.x * blockDim.x + threadIdx.x) >> 5;
    int lane = threadIdx.x & 31;
    if (warp >= D1) return;
    const float4* vp = (const float4*)(W1 + (size_t)warp * D_);
    float4 v0 = vp[lane * 2], v1 = vp[lane * 2 + 1];
    float s = v0.x * v0.x + v0.y * v0.y + v0.z * v0.z + v0.w * v0.w
            + v1.x * v1.x + v1.y * v1.y + v1.z * v1.z + v1.w * v1.w;
#pragma unroll
    for (int o = 16; o; o >>= 1) s += __shfl_xor_sync(0xffffffffu, s, o);
    if (lane == 0) g_invn1[warp] = rsqrtf(s);
}

__global__ void dist1_fill()
{
    int i = blockIdx.x * 256 + threadIdx.x;
    int b = i >> 10, j = i & 1023;
    g_dists[b * NDIST + j] = fabsf(g_z1[i]) * g_invn1[j];
}

// ---------------- HMMA masked batched GEMM + fused epilogue ----------------
// C[b] (128m x 256n fp32) = sum_k (A[m,k]*mask[b,k]) * Bop[b][n,k]   (bf16 MMA)
// Epilogue: dist(doff+m) = |z[b,m]| / ||C row||; optionally write C^T bf16 (V2T).
// Tiles: BM=128, BN=256 (full N), BK=32; 512 threads = 4(M) x 4(N) warps,
// warp tile 32x64 via mma.m16n8k16.
#define STG_A 10240              // 128 x 40 bf16
#define STG_B 20480              // 256 x 40 bf16
#define STG   (STG_A + STG_B)    // 30720
#define SQ_OFF 67584             // after CsT (128*132*4)
#define SMEM_HM (SQ_OFF + 2048)

__global__ __launch_bounds__(512, 1) void hmma_masked(
    const __nv_bfloat16* __restrict__ Ag, const __nv_bfloat16* __restrict__ Bg,
    size_t bstrideB, const __nv_bfloat16* __restrict__ maskb,
    const float* __restrict__ z, int K, int Mtot, int doff,
    __nv_bfloat16* __restrict__ VT)
{
    extern __shared__ __align__(16) char smem[];
    const uint32_t sb = smem_u32(smem);
    const int tid = threadIdx.x, wid = tid >> 5, lane = tid & 31;
    const int warpM = wid >> 2, warpN = wid & 3;
    const int b = blockIdx.y, m0 = blockIdx.x * 128;

    const __nv_bfloat16* mrow = maskb + (size_t)b * K;
    const __nv_bfloat16* Bb = Bg + (size_t)b * bstrideB;

    const int arow = tid >> 2, aseg = tid & 3;       // A: 128 rows x 4 segs(16B)
    const int brow = tid >> 1, bs0 = (tid & 1) * 2;  // B: 256 rows x 4 segs, 2/thr

    const int nch = K >> 5;

    float c[2][8][4];
#pragma unroll
    for (int i = 0; i < 2; i++)
#pragma unroll
        for (int j = 0; j < 8; j++)
#pragma unroll
            for (int r = 0; r < 4; r++) c[i][j][r] = 0.f;

    // ---- prologue: chunk 0 ----
    uint4 av, mv;
    {
        av = *(const uint4*)(Ag + (size_t)(m0 + arow) * K + aseg * 8);
        mv = *(const uint4*)(mrow + aseg * 8);
        uint32_t bdst = sb + STG_A + (uint32_t)brow * 80;
        cpasync16(bdst + (bs0 + 0) * 16, Bb + (size_t)brow * K + (bs0 + 0) * 8);
        cpasync16(bdst + (bs0 + 1) * 16, Bb + (size_t)brow * K + (bs0 + 1) * 8);
        asm volatile("cp.async.commit_group;" ::: "memory");
        __nv_bfloat162* ap = (__nv_bfloat162*)&av;
        const __nv_bfloat162* mp = (const __nv_bfloat162*)&mv;
#pragma unroll
        for (int i = 0; i < 4; i++) ap[i] = __hmul2(ap[i], mp[i]);
        *(uint4*)(smem + (uint32_t)arow * 80 + aseg * 16) = av;
    }

    const int lane15 = lane & 15, laneH8 = (lane >> 4) * 8;

    for (int cidx = 0; cidx < nch; cidx++) {
        int cur = cidx & 1, nxt = cur ^ 1;
        bool more = (cidx + 1 < nch);
        if (more) {
            int k0 = (cidx + 1) << 5;
            av = *(const uint4*)(Ag + (size_t)(m0 + arow) * K + k0 + aseg * 8);
            mv = *(const uint4*)(mrow + k0 + aseg * 8);
            uint32_t bdst = sb + nxt * STG + STG_A + (uint32_t)brow * 80;
            cpasync16(bdst + (bs0 + 0) * 16, Bb + (size_t)brow * K + k0 + (bs0 + 0) * 8);
            cpasync16(bdst + (bs0 + 1) * 16, Bb + (size_t)brow * K + k0 + (bs0 + 1) * 8);
            asm volatile("cp.async.commit_group;" ::: "memory");
            asm volatile("cp.async.wait_group 1;" ::: "memory");
        } else {
            asm volatile("cp.async.wait_group 0;" ::: "memory");
        }
        __syncthreads();

        // ---- compute chunk cur ----
        uint32_t aBase = sb + cur * STG;
        uint32_t bBase = aBase + STG_A;
#pragma unroll
        for (int ks = 0; ks < 2; ks++) {
            uint32_t a0[4], a1[4];
            ldm4(a0, aBase + ((warpM * 32 + lane15) * 40 + ks * 16 + laneH8) * 2);
            ldm4(a1, aBase + ((warpM * 32 + 16 + lane15) * 40 + ks * 16 + laneH8) * 2);
#pragma unroll
            for (int gi = 0; gi < 4; gi++) {
                uint32_t bb[4];
                ldm4(bb, bBase + ((warpN * 64 + gi * 16 + lane15) * 40 + ks * 16 + laneH8) * 2);
                mma16816(c[0][gi * 2],     a0, bb[0], bb[2]);
                mma16816(c[0][gi * 2 + 1], a0, bb[1], bb[3]);
                mma16816(c[1][gi * 2],     a1, bb[0], bb[2]);
                mma16816(c[1][gi * 2 + 1], a1, bb[1], bb[3]);
            }
        }

        if (more) {
            __nv_bfloat162* ap = (__nv_bfloat162*)&av;
            const __nv_bfloat162* mp = (const __nv_bfloat162*)&mv;
#pragma unroll
            for (int i = 0; i < 4; i++) ap[i] = __hmul2(ap[i], mp[i]);
            *(uint4*)(smem + nxt * STG + (uint32_t)arow * 80 + aseg * 16) = av;
        }
    }

    // ---- row sum-of-squares (deterministic) ----
    float* sqsm = (float*)(smem + SQ_OFF);   // [4 warpN][128 rows]
    {
        float rs[2][2] = {{0.f, 0.f}, {0.f, 0.f}};
#pragma unroll
        for (int mi = 0; mi < 2; mi++)
#pragma unroll
            for (int nj = 0; nj < 8; nj++)
#pragma unroll
                for (int r = 0; r < 4; r++) {
                    float v = c[mi][nj][r];
                    rs[mi][r >> 1] += v * v;
                }
#pragma unroll
        for (int mi = 0; mi < 2; mi++)
#pragma unroll
            for (int h = 0; h < 2; h++) {
                float v = rs[mi][h];
                v += __shfl_xor_sync(0xffffffffu, v, 1);
                v += __shfl_xor_sync(0xffffffffu, v, 2);
                rs[mi][h] = v;
            }
        __syncthreads();    // mainloop smem reads done before sqsm writes? sqsm disjoint; sync for store order below
        if ((lane & 3) == 0) {
#pragma unroll
            for (int mi = 0; mi < 2; mi++)
#pragma unroll
                for (int h = 0; h < 2; h++)
                    sqsm[warpN * 128 + warpM * 32 + mi * 16 + h * 8 + (lane >> 2)] = rs[mi][h];
        }
    }
    __syncthreads();
    if (tid < 128) {
        float s = sqsm[tid] + sqsm[128 + tid] + sqsm[256 + tid] + sqsm[384 + tid];
        int mg = m0 + tid;
        g_dists[(size_t)b * NDIST + doff + mg] =
            fabsf(z[(size_t)b * Mtot + mg]) * rsqrtf(s);
    }

    // ---- V^T bf16 writeback (layer 2 only) ----
    if (VT) {
        float* CsT = (float*)smem;           // [128 cols][132 rows]
#pragma unroll 1
        for (int p = 0; p < 2; p++) {
            __syncthreads();
            if ((warpN >> 1) == p) {
                int cbase = (warpN & 1) * 64;
#pragma unroll
                for (int mi = 0; mi < 2; mi++)
#pragma unroll
                    for (int nj = 0; nj < 8; nj++)
#pragma unroll
                        for (int r = 0; r < 4; r++) {
                            int col = cbase + nj * 8 + (lane & 3) * 2 + (r & 1);
                            int row = warpM * 32 + mi * 16 + (r >> 1) * 8 + (lane >> 2);
                            CsT[(size_t)col * 132 + row] = c[mi][nj][r];
                        }
            }
            __syncthreads();
            int d = tid >> 2;
#pragma unroll
            for (int rr = 0; rr < 4; rr++) {
                int seg = (tid & 3) + rr * 4;
                const float* cp = &CsT[(size_t)d * 132 + seg * 8];
                float4 v0 = *(const float4*)cp;
                float4 v1 = *(const float4*)(cp + 4);
                __nv_bfloat16 hv[8];
                hv[0] = __float2bfloat16(v0.x); hv[1] = __float2bfloat16(v0.y);
                hv[2] = __float2bfloat16(v0.z); hv[3] = __float2bfloat16(v0.w);
                hv[4] = __float2bfloat16(v1.x); hv[5] = __float2bfloat16(v1.y);
                hv[6] = __float2bfloat16(v1.z); hv[7] = __float2bfloat16(v1.w);
                size_t ofs = ((size_t)b * D_ + p * 128 + d) * (size_t)Mtot + m0 + seg * 8;
                *(uint4*)(VT + ofs) = *(uint4*)hv;
            }
        }
    }
}

// ---------------- per-batch smallest-k sum ----------------------------------
__global__ void topk_kernel()
{
    __shared__ float s[NDIST];
    __shared__ float rv[256];
    __shared__ int   ri[256];
    int b = blockIdx.x, t = threadIdx.x;
    for (int i = t; i < NDIST; i += 256) s[i] = g_dists[b * NDIST + i];
    __syncthreads();
    float tot = 0.f;
    for (int it = 0; it < KSEL; it++) {
        float best = 3.402823466e38f; int bi = NDIST;
        for (int i = t; i < NDIST; i += 256) {
            float v = s[i];
            if (v < best) { best = v; bi = i; }
        }
        rv[t] = best; ri[t] = bi;
        __syncthreads();
        for (int st = 128; st > 0; st >>= 1) {
            if (t < st) {
                if (rv[t + st] < rv[t] ||
                    (rv[t + st] == rv[t] && ri[t + st] < ri[t])) {
                    rv[t] = rv[t + st]; ri[t] = ri[t + st];
                }
            }
            __syncthreads();
        }
        if (t == 0) { tot += rv[0]; s[ri[0]] = 3.402823466e38f; }
        __syncthreads();
    }
    if (t == 0) g_partial[b] = tot;
}

__global__ void final_reduce(float* __restrict__ out)
{
    __shared__ float sh[256];
    int t = threadIdx.x;
    sh[t] = g_partial[t];
    __syncthreads();
    for (int st = 128; st > 0; st >>= 1) {
        if (t < st) sh[t] += sh[t + st];
        __syncthreads();
    }
    if (t == 0) out[0] = sh[0];
}

// ---------------- launch -----------------------------------------------------
extern "C" void kernel_launch(void* const* d_in, const int* in_sizes, int n_in,
                              void* d_out, int out_size)
{
    const float* x  = (const float*)d_in[0];
    const float* W1 = (const float*)d_in[1];
    const float* b1 = (const float*)d_in[2];
    const float* W2 = (const float*)d_in[3];
    const float* b2 = (const float*)d_in[4];
    const float* W3 = (const float*)d_in[5];
    const float* b3 = (const float*)d_in[6];
    float* out = (float*)d_out;

    float *z1p, *h1p, *z2p, *h2p, *z3p;
    __nv_bfloat16 *m1p, *m2p, *w2h, *w3h, *w1th, *v2t;
    cudaGetSymbolAddress((void**)&z1p, g_z1);
    cudaGetSymbolAddress((void**)&h1p, g_h1);
    cudaGetSymbolAddress((void**)&m1p, g_m1b);
    cudaGetSymbolAddress((void**)&z2p, g_z2);
    cudaGetSymbolAddress((void**)&h2p, g_h2);
    cudaGetSymbolAddress((void**)&m2p, g_m2b);
    cudaGetSymbolAddress((void**)&z3p, g_z3);
    cudaGetSymbolAddress((void**)&w2h, g_W2h);
    cudaGetSymbolAddress((void**)&w3h, g_W3h);
    cudaGetSymbolAddress((void**)&w1th, g_W1Th);
    cudaGetSymbolAddress((void**)&v2t, g_V2T);

    cudaFuncSetAttribute(hmma_masked,
                         cudaFuncAttributeMaxDynamicSharedMemorySize, SMEM_HM);

    // weight preprocessing
    to_bf16<<<(D2 * D1 + 255) / 256, 256>>>(W2, w2h, D2 * D1);
    to_bf16<<<(D3 * D2 + 255) / 256, 256>>>(W3, w3h, D3 * D2);
    w1t_cast<<<(D_ * D1) / 256, 256>>>(W1);
    w1norm<<<D1 / 8, 256>>>(W1);

    // forward pass (exact fp32 so masks match the reference)
    zgemm_nt<<<dim3(D1 / 64, B_ / 64), 256>>>(x,   W1, b1, B_, D1, D_,  z1p, h1p, m1p);
    zgemm_nt<<<dim3(D2 / 64, B_ / 64), 256>>>(h1p, W2, b2, B_, D2, D1, z2p, h2p, m2p);
    zgemm_nt<<<dim3(D3 / 64, B_ / 64), 256>>>(h2p, W3, b3, B_, D3, D2, z3p,
                                              (float*)0, (__nv_bfloat16*)0);

    dist1_fill<<<(B_ * D1) / 256, 256>>>();

    // layer-2: V2[b] = (W2 o m1[b]) @ W1  -> dist2 + V2^T bf16
    hmma_masked<<<dim3(D2 / 128, B_), 512, SMEM_HM>>>(
        w2h, w1th, (size_t)0, m1p, z2p, D1, D2, D1, v2t);

    // layer-3: V3[b] = (W3 o m2[b]) @ V2[b] -> dist3 only
    hmma_masked<<<dim3(D3 / 128, B_), 512, SMEM_HM>>>(
        w3h, v2t, (size_t)D_ * D2, m2p, z3p, D2, D3, D1 + D2,
        (__nv_bfloat16*)0);

    topk_kernel<<<B_, 256>>>();
    final_reduce<<<1, 256>>>(out);
}

// round 5
// speedup vs baseline: 5.1323x; 1.2788x over previous
#include <cuda_runtime.h>
#include <cuda_bf16.h>
#include <math.h>
#include <stdint.h>

// Problem dims (fixed by setup_inputs)
#define B_   256
#define D_   256
#define D1   1024
#define D2   512
#define D3   256
#define NDIST (D1 + D2 + D3)   // 1792
#define KSEL 10

// ---------------- scratch (device globals; no cudaMalloc allowed) ----------
__device__ float g_z1[B_ * D1];
__device__ float g_h1[B_ * D1];
__device__ float g_z2[B_ * D2];
__device__ float g_h2[B_ * D2];
__device__ float g_z3[B_ * D3];
__device__ __nv_bfloat16 g_W2T[(D1 + 1) * D2];            // [1025][512], row 1024 = 0
__device__ __nv_bfloat16 g_W3T[(D2 + 1) * D3];            // [513][256],  row 512  = 0
__device__ __nv_bfloat16 g_W1b[D1 * D_];                  // [1024][256]
__device__ __nv_bfloat16 g_V2[(size_t)B_ * D2 * D_];      // [B][512][256] row-major
__device__ int g_kidx1[B_ * (D1 + 32)];
__device__ int g_cnt1[B_];
__device__ int g_kidx2[B_ * (D2 + 32)];
__device__ int g_cnt2[B_];
__device__ float g_invn1[D1];
__device__ float g_dists[B_ * NDIST];
__device__ float g_partial[B_];

// ---------------- PTX helpers ------------------------------------------------
__device__ __forceinline__ uint32_t smem_u32(const void* p) {
    uint32_t a;
    asm("{ .reg .u64 t; cvta.to.shared.u64 t, %1; cvt.u32.u64 %0, t; }"
        : "=r"(a) : "l"(p));
    return a;
}
__device__ __forceinline__ void cpasync16(uint32_t dst, const void* src) {
    asm volatile("cp.async.cg.shared.global [%0], [%1], 16;"
                 :: "r"(dst), "l"(src) : "memory");
}
__device__ __forceinline__ void ldm4t(uint32_t r[4], uint32_t addr) {
    asm volatile("ldmatrix.sync.aligned.m8n8.x4.trans.shared.b16 {%0,%1,%2,%3}, [%4];"
                 : "=r"(r[0]), "=r"(r[1]), "=r"(r[2]), "=r"(r[3]) : "r"(addr));
}
__device__ __forceinline__ void mma16816(float* c, const uint32_t a[4],
                                         uint32_t b0, uint32_t b1) {
    asm volatile(
        "mma.sync.aligned.m16n8k16.row.col.f32.bf16.bf16.f32 "
        "{%0,%1,%2,%3}, {%4,%5,%6,%7}, {%8,%9}, {%0,%1,%2,%3};"
        : "+f"(c[0]), "+f"(c[1]), "+f"(c[2]), "+f"(c[3])
        : "r"(a[0]), "r"(a[1]), "r"(a[2]), "r"(a[3]), "r"(b0), "r"(b1));
}

// ---------------- forward-pass GEMM: Z = X @ W^T + bias --------------------
__global__ __launch_bounds__(256) void zgemm_nt(
    const float* __restrict__ X, const float* __restrict__ W,
    const float* __restrict__ bias, int M, int N, int K,
    float* __restrict__ Z, float* __restrict__ H)
{
    const int BM = 64, BN = 64, BK = 16;
    __shared__ __align__(16) float Xs[BK][BM];
    __shared__ __align__(16) float Ws[BK][BN];

    int m0 = blockIdx.y * BM, n0 = blockIdx.x * BN;
    int tid = threadIdx.x;
    int tx = tid & 15, ty = tid >> 4;
    int lrow = tid >> 2, lcol = (tid & 3) * 4;

    float acc[4][4];
#pragma unroll
    for (int i = 0; i < 4; i++)
#pragma unroll
        for (int j = 0; j < 4; j++) acc[i][j] = 0.f;

    for (int k0 = 0; k0 < K; k0 += BK) {
        float4 xa = *(const float4*)(X + (size_t)(m0 + lrow) * K + k0 + lcol);
        float4 wa = *(const float4*)(W + (size_t)(n0 + lrow) * K + k0 + lcol);
        __syncthreads();
        Xs[lcol + 0][lrow] = xa.x; Xs[lcol + 1][lrow] = xa.y;
        Xs[lcol + 2][lrow] = xa.z; Xs[lcol + 3][lrow] = xa.w;
        Ws[lcol + 0][lrow] = wa.x; Ws[lcol + 1][lrow] = wa.y;
        Ws[lcol + 2][lrow] = wa.z; Ws[lcol + 3][lrow] = wa.w;
        __syncthreads();
#pragma unroll
        for (int k = 0; k < BK; k++) {
            float4 av = *(float4*)&Xs[k][ty * 4];
            float4 wv = *(float4*)&Ws[k][tx * 4];
            float a[4] = {av.x, av.y, av.z, av.w};
            float w[4] = {wv.x, wv.y, wv.z, wv.w};
#pragma unroll
            for (int i = 0; i < 4; i++)
#pragma unroll
                for (int j = 0; j < 4; j++) acc[i][j] += a[i] * w[j];
        }
    }

#pragma unroll
    for (int i = 0; i < 4; i++) {
        int m = m0 + ty * 4 + i;
#pragma unroll
        for (int j = 0; j < 4; j++) {
            int n = n0 + tx * 4 + j;
            float zv = acc[i][j] + bias[n];
            size_t o = (size_t)m * N + n;
            Z[o] = zv;
            if (H) H[o] = zv > 0.f ? zv : 0.f;
        }
    }
}

// ---------------- precompute kernels ----------------------------------------
// W2 [512][1024] -> W2T [1025][512] bf16 (row 1024 = zeros)
__global__ void w2t_cast(const float* __restrict__ W2)
{
    int i = blockIdx.x * 256 + threadIdx.x;
    if (i >= (D1 + 1) * D2) return;
    int k = i >> 9, m = i & 511;
    g_W2T[i] = (k < D1) ? __float2bfloat16(W2[(size_t)m * D1 + k])
                        : __float2bfloat16(0.f);
}
// W3 [256][512] -> W3T [513][256] bf16 (row 512 = zeros)
__global__ void w3t_cast(const float* __restrict__ W3)
{
    int i = blockIdx.x * 256 + threadIdx.x;
    if (i >= (D2 + 1) * D3) return;
    int k = i >> 8, m = i & 255;
    g_W3T[i] = (k < D2) ? __float2bfloat16(W3[(size_t)m * D2 + k])
                        : __float2bfloat16(0.f);
}
__global__ void w1_cast(const float* __restrict__ W1)
{
    int i = blockIdx.x * 256 + threadIdx.x;
    if (i < D1 * D_) g_W1b[i] = __float2bfloat16(W1[i]);
}

__global__ void w1norm(const float* __restrict__ W1)
{
    int warp = (blockIdx.x * blockDim.x + threadIdx.x) >> 5;
    int lane = threadIdx.x & 31;
    if (warp >= D1) return;
    const float4* vp = (const float4*)(W1 + (size_t)warp * D_);
    float4 v0 = vp[lane * 2], v1 = vp[lane * 2 + 1];
    float s = v0.x * v0.x + v0.y * v0.y + v0.z * v0.z + v0.w * v0.w
            + v1.x * v1.x + v1.y * v1.y + v1.z * v1.z + v1.w * v1.w;
#pragma unroll
    for (int o = 16; o; o >>= 1) s += __shfl_xor_sync(0xffffffffu, s, o);
    if (lane == 0) g_invn1[warp] = rsqrtf(s);
}

__global__ void dist1_fill()
{
    int i = blockIdx.x * 256 + threadIdx.x;
    int b = i >> 10, j = i & 1023;
    g_dists[b * NDIST + j] = fabsf(g_z1[i]) * g_invn1[j];
}

// ---------------- deterministic per-batch active-k compaction ---------------
template <int KN>
__global__ void compact_k(const float* __restrict__ z,
                          int* __restrict__ kidx, int* __restrict__ cnt)
{
    const int E = KN / 256;
    const int kpitch = KN + 32;
    __shared__ int sh[256];
    int b = blockIdx.x, t = threadIdx.x;
    int flag[E];
    int c = 0;
#pragma unroll
    for (int e = 0; e < E; e++) {
        flag[e] = (z[(size_t)b * KN + t * E + e] > 0.f) ? 1 : 0;
        c += flag[e];
    }
    sh[t] = c;
    __syncthreads();
    for (int s = 1; s < 256; s <<= 1) {
        int x = (t >= s) ? sh[t - s] : 0;
        __syncthreads();
        sh[t] += x;
        __syncthreads();
    }
    int pos = sh[t] - c;
#pragma unroll
    for (int e = 0; e < E; e++)
        if (flag[e]) kidx[(size_t)b * kpitch + pos++] = t * E + e;
    int total = sh[255];
    int padded = (total + 31) & ~31;
    int ip = total + t;
    if (ip < padded) kidx[(size_t)b * kpitch + ip] = KN;  // -> zero row of A^T
    if (t == 0) cnt[b] = total;
}

// ---------------- HMMA k-compacted batched GEMM + fused epilogue ------------
// C[b] (128m x 256n fp32) = sum_{k in kidx[b]} AT[k][m] * Bk[b][k][n]
// AT [K+1][Mtot] bf16 k-major (zero pad row); Bk rows [*][256] bf16 k-major.
// Epilogue: dist(doff+m) = |z[b,m]| * rsqrt(||C row||^2); optional V (=C) bf16.
#define APITCH 272               // 32k x 128m bf16 rows padded to 272B
#define BPITCH 528               // 32k x 256n bf16 rows padded to 528B
#define ASTG   (32 * APITCH)     // 8704
#define BSTG   (32 * BPITCH)     // 16896
#define STGC   (ASTG + BSTG)     // 25600
#define SQOFF  (2 * STGC)        // 51200
#define SMEMC  (SQOFF + 2048)

__global__ __launch_bounds__(512, 1) void hmma_comp(
    const __nv_bfloat16* __restrict__ AT, const __nv_bfloat16* __restrict__ Bk,
    size_t bstrideB, int bclamp,
    const int* __restrict__ kidx, const int* __restrict__ cnt, int kpitch,
    const float* __restrict__ z, int Mtot, int doff,
    __nv_bfloat16* __restrict__ Vout)
{
    extern __shared__ __align__(16) char smem[];
    const uint32_t sb = smem_u32(smem);
    const int tid = threadIdx.x, wid = tid >> 5, lane = tid & 31;
    const int warpM = wid >> 2, warpN = wid & 3;
    const int b = blockIdx.y, m0 = blockIdx.x * 128;

    const __nv_bfloat16* Bb = Bk + (size_t)b * bstrideB;
    const int* kp = kidx + (size_t)b * kpitch;
    const int nch = (cnt[b] + 31) >> 5;

    float c[2][8][4];
#pragma unroll
    for (int i = 0; i < 2; i++)
#pragma unroll
        for (int j = 0; j < 8; j++)
#pragma unroll
            for (int r = 0; r < 4; r++) c[i][j][r] = 0.f;

    const int gr = tid >> 4;          // 0..31: gathered row within chunk
    const int aseg = tid & 15;        // A: 16 x 16B segments
    const int bsg = (tid & 15) * 2;   // B: 2 x 16B segments per thread

    auto load_stage = [&](int s, int cc) {
        uint32_t st = sb + s * STGC;
        const int* kc = kp + cc * 32;
        int k = __ldg(kc + gr);
        cpasync16(st + gr * APITCH + aseg * 16,
                  AT + (size_t)k * Mtot + m0 + aseg * 8);
        int kb = min(k, bclamp);
        const __nv_bfloat16* src = Bb + (size_t)kb * 256 + bsg * 8;
        cpasync16(st + ASTG + gr * BPITCH + bsg * 16, src);
        cpasync16(st + ASTG + gr * BPITCH + bsg * 16 + 16, src + 8);
        asm volatile("cp.async.commit_group;" ::: "memory");
    };

    if (nch > 0) {
        load_stage(0, 0);

        const int kr = (lane & 7) + ((lane >> 4) << 3);  // k-row within 16-blk
        const int ch8 = ((lane >> 3) & 1) << 3;          // +8 col for odd octet

        for (int cidx = 0; cidx < nch; cidx++) {
            int cur = cidx & 1;
            if (cidx + 1 < nch) {
                load_stage(cur ^ 1, cidx + 1);
                asm volatile("cp.async.wait_group 1;" ::: "memory");
            } else {
                asm volatile("cp.async.wait_group 0;" ::: "memory");
            }
            __syncthreads();

            uint32_t aBase = sb + cur * STGC;
            uint32_t bBase = aBase + ASTG;
#pragma unroll
            for (int ks = 0; ks < 2; ks++) {
                uint32_t arow = aBase + (uint32_t)(ks * 16 + kr) * APITCH;
                uint32_t brow = bBase + (uint32_t)(ks * 16 + kr) * BPITCH;
                uint32_t a0[4], a1[4];
                ldm4t(a0, arow + (uint32_t)(warpM * 32 + ch8) * 2);
                ldm4t(a1, arow + (uint32_t)(warpM * 32 + 16 + ch8) * 2);
#pragma unroll
                for (int gi = 0; gi < 4; gi++) {
                    uint32_t bb[4];
                    ldm4t(bb, brow + (uint32_t)(warpN * 64 + gi * 16 + ch8) * 2);
                    mma16816(c[0][gi * 2],     a0, bb[0], bb[2]);
                    mma16816(c[0][gi * 2 + 1], a0, bb[1], bb[3]);
                    mma16816(c[1][gi * 2],     a1, bb[0], bb[2]);
                    mma16816(c[1][gi * 2 + 1], a1, bb[1], bb[3]);
                }
            }
            __syncthreads();
        }
    }

    // ---- row sum-of-squares (deterministic order) ----
    float* sqsm = (float*)(smem + SQOFF);   // [4 warpN][128 rows]
    {
        float rs[2][2] = {{0.f, 0.f}, {0.f, 0.f}};
#pragma unroll
        for (int mi = 0; mi < 2; mi++)
#pragma unroll
            for (int nj = 0; nj < 8; nj++)
#pragma unroll
                for (int r = 0; r < 4; r++) {
                    float v = c[mi][nj][r];
                    rs[mi][r >> 1] += v * v;
                }
#pragma unroll
        for (int mi = 0; mi < 2; mi++)
#pragma unroll
            for (int h = 0; h < 2; h++) {
                float v = rs[mi][h];
                v += __shfl_xor_sync(0xffffffffu, v, 1);
                v += __shfl_xor_sync(0xffffffffu, v, 2);
                rs[mi][h] = v;
            }
        if ((lane & 3) == 0) {
#pragma unroll
            for (int mi = 0; mi < 2; mi++)
#pragma unroll
                for (int h = 0; h < 2; h++)
                    sqsm[warpN * 128 + warpM * 32 + mi * 16 + h * 8 + (lane >> 2)]
                        = rs[mi][h];
        }
    }
    __syncthreads();
    if (tid < 128) {
        float s = sqsm[tid] + sqsm[128 + tid] + sqsm[256 + tid] + sqsm[384 + tid];
        int mg = m0 + tid;
        g_dists[(size_t)b * NDIST + doff + mg] =
            fabsf(z[(size_t)b * Mtot + mg]) * rsqrtf(s);
    }

    // ---- V writeback (row-major C, layer 2 only) ----
    if (Vout) {
        __nv_bfloat16* Vb = Vout + (size_t)b * Mtot * 256;
#pragma unroll
        for (int mi = 0; mi < 2; mi++)
#pragma unroll
            for (int nj = 0; nj < 8; nj++)
#pragma unroll
                for (int rp = 0; rp < 2; rp++) {
                    int row = m0 + warpM * 32 + mi * 16 + rp * 8 + (lane >> 2);
                    int col = warpN * 64 + nj * 8 + (lane & 3) * 2;
                    __nv_bfloat162 p;
                    p.x = __float2bfloat16(c[mi][nj][rp * 2]);
                    p.y = __float2bfloat16(c[mi][nj][rp * 2 + 1]);
                    *(__nv_bfloat162*)(Vb + (size_t)row * 256 + col) = p;
                }
    }
}

// ---------------- per-batch smallest-k sum ----------------------------------
__global__ void topk_kernel()
{
    __shared__ float s[NDIST];
    __shared__ float rv[256];
    __shared__ int   ri[256];
    int b = blockIdx.x, t = threadIdx.x;
    for (int i = t; i < NDIST; i += 256) s[i] = g_dists[b * NDIST + i];
    __syncthreads();
    float tot = 0.f;
    for (int it = 0; it < KSEL; it++) {
        float best = 3.402823466e38f; int bi = NDIST;
        for (int i = t; i < NDIST; i += 256) {
            float v = s[i];
            if (v < best) { best = v; bi = i; }
        }
        rv[t] = best; ri[t] = bi;
        __syncthreads();
        for (int st = 128; st > 0; st >>= 1) {
            if (t < st) {
                if (rv[t + st] < rv[t] ||
                    (rv[t + st] == rv[t] && ri[t + st] < ri[t])) {
                    rv[t] = rv[t + st]; ri[t] = ri[t + st];
                }
            }
            __syncthreads();
        }
        if (t == 0) { tot += rv[0]; s[ri[0]] = 3.402823466e38f; }
        __syncthreads();
    }
    if (t == 0) g_partial[b] = tot;
}

__global__ void final_reduce(float* __restrict__ out)
{
    __shared__ float sh[256];
    int t = threadIdx.x;
    sh[t] = g_partial[t];
    __syncthreads();
    for (int st = 128; st > 0; st >>= 1) {
        if (t < st) sh[t] += sh[t + st];
        __syncthreads();
    }
    if (t == 0) out[0] = sh[0];
}

// ---------------- launch -----------------------------------------------------
extern "C" void kernel_launch(void* const* d_in, const int* in_sizes, int n_in,
                              void* d_out, int out_size)
{
    const float* x  = (const float*)d_in[0];
    const float* W1 = (const float*)d_in[1];
    const float* b1 = (const float*)d_in[2];
    const float* W2 = (const float*)d_in[3];
    const float* b2 = (const float*)d_in[4];
    const float* W3 = (const float*)d_in[5];
    const float* b3 = (const float*)d_in[6];
    float* out = (float*)d_out;

    float *z1p, *h1p, *z2p, *h2p, *z3p;
    __nv_bfloat16 *w2t, *w3t, *w1b, *v2;
    int *ki1, *ci1, *ki2, *ci2;
    cudaGetSymbolAddress((void**)&z1p, g_z1);
    cudaGetSymbolAddress((void**)&h1p, g_h1);
    cudaGetSymbolAddress((void**)&z2p, g_z2);
    cudaGetSymbolAddress((void**)&h2p, g_h2);
    cudaGetSymbolAddress((void**)&z3p, g_z3);
    cudaGetSymbolAddress((void**)&w2t, g_W2T);
    cudaGetSymbolAddress((void**)&w3t, g_W3T);
    cudaGetSymbolAddress((void**)&w1b, g_W1b);
    cudaGetSymbolAddress((void**)&v2,  g_V2);
    cudaGetSymbolAddress((void**)&ki1, g_kidx1);
    cudaGetSymbolAddress((void**)&ci1, g_cnt1);
    cudaGetSymbolAddress((void**)&ki2, g_kidx2);
    cudaGetSymbolAddress((void**)&ci2, g_cnt2);

    cudaFuncSetAttribute(hmma_comp,
                         cudaFuncAttributeMaxDynamicSharedMemorySize, SMEMC);

    // launches 1..5 (so hmma layer-2 is launch #6 for ncu -s 5 -c 1)
    w2t_cast<<<((D1 + 1) * D2 + 255) / 256, 256>>>(W2);
    w1_cast<<<(D1 * D_) / 256, 256>>>(W1);
    zgemm_nt<<<dim3(D1 / 64, B_ / 64), 256>>>(x,   W1, b1, B_, D1, D_,  z1p, h1p);
    compact_k<D1><<<B_, 256>>>(z1p, ki1, ci1);
    zgemm_nt<<<dim3(D2 / 64, B_ / 64), 256>>>(h1p, W2, b2, B_, D2, D1, z2p, h2p);

    // #6: layer-2  V2[b] = (W2 o m1[b]) @ W1  -> dist2 + V2 bf16 (row-major)
    hmma_comp<<<dim3(D2 / 128, B_), 512, SMEMC>>>(
        w2t, w1b, (size_t)0, D1 - 1, ki1, ci1, D1 + 32,
        z2p, D2, D1, v2);

    w3t_cast<<<((D2 + 1) * D3 + 255) / 256, 256>>>(W3);
    zgemm_nt<<<dim3(D3 / 64, B_ / 64), 256>>>(h2p, W3, b3, B_, D3, D2, z3p, (float*)0);
    compact_k<D2><<<B_, 256>>>(z2p, ki2, ci2);

    // layer-3  V3[b] = (W3 o m2[b]) @ V2[b]  -> dist3 only
    hmma_comp<<<dim3(D3 / 128, B_), 512, SMEMC>>>(
        w3t, v2, (size_t)D2 * D_, D2 - 1, ki2, ci2, D2 + 32,
        z3p, D3, D1 + D2, (__nv_bfloat16*)0);

    w1norm<<<D1 / 8, 256>>>(W1);
    dist1_fill<<<(B_ * D1) / 256, 256>>>();
    topk_kernel<<<B_, 256>>>();
    final_reduce<<<1, 256>>>(out);
}

// round 6
// speedup vs baseline: 5.7960x; 1.1293x over previous
#include <cuda_runtime.h>
#include <cuda_bf16.h>
#include <math.h>
#include <stdint.h>

// Problem dims (fixed by setup_inputs)
#define B_   256
#define D_   256
#define D1   1024
#define D2   512
#define D3   256
#define NDIST (D1 + D2 + D3)   // 1792
#define KSEL 10

// ---------------- scratch (device globals; no cudaMalloc allowed) ----------
__device__ float g_z1[B_ * D1];
__device__ float g_h1[B_ * D1];
__device__ float g_z2[B_ * D2];
__device__ float g_h2[B_ * D2];
__device__ float g_z3[B_ * D3];
__device__ __nv_bfloat16 g_W2T[(D1 + 1) * D2];            // [1025][512], row 1024 = 0
__device__ __nv_bfloat16 g_W3T[(D2 + 1) * D3];            // [513][256],  row 512  = 0
__device__ __nv_bfloat16 g_W1b[D1 * D_];                  // [1024][256]
__device__ __nv_bfloat16 g_V2[(size_t)B_ * D2 * D_];      // [B][512][256] row-major
__device__ int g_kidx1[B_ * (D1 + 32)];
__device__ int g_cnt1[B_];
__device__ int g_kidx2[B_ * (D2 + 32)];
__device__ int g_cnt2[B_];
__device__ float g_invn1[D1];
__device__ float g_dists[B_ * NDIST];
__device__ float g_partial[B_];

// ---------------- PTX helpers ------------------------------------------------
__device__ __forceinline__ uint32_t smem_u32(const void* p) {
    uint32_t a;
    asm("{ .reg .u64 t; cvta.to.shared.u64 t, %1; cvt.u32.u64 %0, t; }"
        : "=r"(a) : "l"(p));
    return a;
}
__device__ __forceinline__ void cpasync16(uint32_t dst, const void* src) {
    asm volatile("cp.async.cg.shared.global [%0], [%1], 16;"
                 :: "r"(dst), "l"(src) : "memory");
}
__device__ __forceinline__ void ldm4t(uint32_t r[4], uint32_t addr) {
    asm volatile("ldmatrix.sync.aligned.m8n8.x4.trans.shared.b16 {%0,%1,%2,%3}, [%4];"
                 : "=r"(r[0]), "=r"(r[1]), "=r"(r[2]), "=r"(r[3]) : "r"(addr));
}
__device__ __forceinline__ void mma16816(float* c, const uint32_t a[4],
                                         uint32_t b0, uint32_t b1) {
    asm volatile(
        "mma.sync.aligned.m16n8k16.row.col.f32.bf16.bf16.f32 "
        "{%0,%1,%2,%3}, {%4,%5,%6,%7}, {%8,%9}, {%0,%1,%2,%3};"
        : "+f"(c[0]), "+f"(c[1]), "+f"(c[2]), "+f"(c[3])
        : "r"(a[0]), "r"(a[1]), "r"(a[2]), "r"(a[3]), "r"(b0), "r"(b1));
}

// ---------------- forward-pass GEMM: Z = X @ W^T + bias --------------------
// BM=32, BN=64, BK=32; 256 threads; 2x4 per-thread microtile.
__global__ __launch_bounds__(256) void zgemm32(
    const float* __restrict__ X, const float* __restrict__ W,
    const float* __restrict__ bias, int M, int N, int K,
    float* __restrict__ Z, float* __restrict__ H)
{
    __shared__ __align__(16) float Xs[32][34];   // [k][m]
    __shared__ __align__(16) float Ws[32][68];   // [k][n]

    int m0 = blockIdx.y * 32, n0 = blockIdx.x * 64;
    int tid = threadIdx.x;
    int tx = tid & 15, ty = tid >> 4;
    int lrow = tid >> 3, lk = (tid & 7) * 4;

    float acc[2][4];
#pragma unroll
    for (int i = 0; i < 2; i++)
#pragma unroll
        for (int j = 0; j < 4; j++) acc[i][j] = 0.f;

    for (int k0 = 0; k0 < K; k0 += 32) {
        float4 xa = *(const float4*)(X + (size_t)(m0 + lrow) * K + k0 + lk);
        float4 w0 = *(const float4*)(W + (size_t)(n0 + lrow) * K + k0 + lk);
        float4 w1 = *(const float4*)(W + (size_t)(n0 + lrow + 32) * K + k0 + lk);
        __syncthreads();
        Xs[lk + 0][lrow] = xa.x; Xs[lk + 1][lrow] = xa.y;
        Xs[lk + 2][lrow] = xa.z; Xs[lk + 3][lrow] = xa.w;
        Ws[lk + 0][lrow] = w0.x; Ws[lk + 1][lrow] = w0.y;
        Ws[lk + 2][lrow] = w0.z; Ws[lk + 3][lrow] = w0.w;
        Ws[lk + 0][lrow + 32] = w1.x; Ws[lk + 1][lrow + 32] = w1.y;
        Ws[lk + 2][lrow + 32] = w1.z; Ws[lk + 3][lrow + 32] = w1.w;
        __syncthreads();
#pragma unroll
        for (int k = 0; k < 32; k++) {
            float a0 = Xs[k][ty * 2], a1 = Xs[k][ty * 2 + 1];
            float4 wv = *(float4*)&Ws[k][tx * 4];
            acc[0][0] += a0 * wv.x; acc[0][1] += a0 * wv.y;
            acc[0][2] += a0 * wv.z; acc[0][3] += a0 * wv.w;
            acc[1][0] += a1 * wv.x; acc[1][1] += a1 * wv.y;
            acc[1][2] += a1 * wv.z; acc[1][3] += a1 * wv.w;
        }
    }

#pragma unroll
    for (int i = 0; i < 2; i++) {
        int m = m0 + ty * 2 + i;
#pragma unroll
        for (int j = 0; j < 4; j++) {
            int n = n0 + tx * 4 + j;
            float zv = acc[i][j] + bias[n];
            size_t o = (size_t)m * N + n;
            Z[o] = zv;
            if (H) H[o] = zv > 0.f ? zv : 0.f;
        }
    }
}

// ---------------- deterministic per-batch active-k compaction (device fn) --
template <int KN>
__device__ __forceinline__ void compact_body(
    const float* __restrict__ z, int* __restrict__ kidx, int* __restrict__ cnt,
    int b, int t)
{
    const int E = KN / 256;
    const int kpitch = KN + 32;
    __shared__ int sh[256];
    int flag[E];
    int c = 0;
#pragma unroll
    for (int e = 0; e < E; e++) {
        flag[e] = (z[(size_t)b * KN + t * E + e] > 0.f) ? 1 : 0;
        c += flag[e];
    }
    sh[t] = c;
    __syncthreads();
    for (int s = 1; s < 256; s <<= 1) {
        int x = (t >= s) ? sh[t - s] : 0;
        __syncthreads();
        sh[t] += x;
        __syncthreads();
    }
    int pos = sh[t] - c;
#pragma unroll
    for (int e = 0; e < E; e++)
        if (flag[e]) kidx[(size_t)b * kpitch + pos++] = t * E + e;
    int total = sh[255];
    int padded = (total + 31) & ~31;
    int ip = total + t;
    if (ip < padded) kidx[(size_t)b * kpitch + ip] = KN;  // -> zero row of A^T
    if (t == 0) cnt[b] = total;
}

// fused: compact(z1) + W2T cast + W1 cast + W1 row inv-norms
// grid = 256 + 2050 + 1024 + 128 = 3458
__global__ void compact1_prep(const float* __restrict__ z1,
                              const float* __restrict__ W1,
                              const float* __restrict__ W2)
{
    int blk = blockIdx.x, t = threadIdx.x;
    if (blk < 256) {
        compact_body<D1>(z1, g_kidx1, g_cnt1, blk, t);
    } else if (blk < 256 + 2050) {
        int i = (blk - 256) * 256 + t;
        if (i < (D1 + 1) * D2) {
            int k = i >> 9, m = i & 511;
            g_W2T[i] = (k < D1) ? __float2bfloat16(W2[(size_t)m * D1 + k])
                                : __float2bfloat16(0.f);
        }
    } else if (blk < 256 + 2050 + 1024) {
        int i = (blk - 256 - 2050) * 256 + t;
        g_W1b[i] = __float2bfloat16(W1[i]);
    } else {
        int warp = (blk - 256 - 2050 - 1024) * 8 + (t >> 5);
        int lane = t & 31;
        const float4* vp = (const float4*)(W1 + (size_t)warp * D_);
        float4 v0 = vp[lane * 2], v1 = vp[lane * 2 + 1];
        float s = v0.x * v0.x + v0.y * v0.y + v0.z * v0.z + v0.w * v0.w
                + v1.x * v1.x + v1.y * v1.y + v1.z * v1.z + v1.w * v1.w;
#pragma unroll
        for (int o = 16; o; o >>= 1) s += __shfl_xor_sync(0xffffffffu, s, o);
        if (lane == 0) g_invn1[warp] = rsqrtf(s);
    }
}

// fused: compact(z2) + W3T cast.  grid = 256 + 513
__global__ void compact2_prep(const float* __restrict__ z2,
                              const float* __restrict__ W3)
{
    int blk = blockIdx.x, t = threadIdx.x;
    if (blk < 256) {
        compact_body<D2>(z2, g_kidx2, g_cnt2, blk, t);
    } else {
        int i = (blk - 256) * 256 + t;
        if (i < (D2 + 1) * D3) {
            int k = i >> 8, m = i & 255;
            g_W3T[i] = (k < D2) ? __float2bfloat16(W3[(size_t)m * D2 + k])
                                : __float2bfloat16(0.f);
        }
    }
}

// ---------------- HMMA k-compacted batched GEMM + fused epilogue ------------
// C[b] (128m x 256n fp32) = sum_{k in kidx[b]} AT[k][m] * Bk[b][k][n]
// AT [K+1][Mtot] bf16 k-major (zero pad row); Bk rows [*][256] bf16 k-major.
// Epilogue: dist(doff+m) = |z[b,m]| * rsqrt(||C row||^2); optional V (=C) bf16.
#define APITCH 272               // 32k x 128m bf16 rows padded to 272B
#define BPITCH 528               // 32k x 256n bf16 rows padded to 528B
#define ASTG   (32 * APITCH)     // 8704
#define BSTG   (32 * BPITCH)     // 16896
#define STGC   (ASTG + BSTG)     // 25600
#define SQOFF  (2 * STGC)        // 51200
#define SMEMC  (SQOFF + 2048)

__global__ __launch_bounds__(512, 1) void hmma_comp(
    const __nv_bfloat16* __restrict__ AT, const __nv_bfloat16* __restrict__ Bk,
    size_t bstrideB, int bclamp,
    const int* __restrict__ kidx, const int* __restrict__ cnt, int kpitch,
    const float* __restrict__ z, int Mtot, int doff,
    __nv_bfloat16* __restrict__ Vout)
{
    extern __shared__ __align__(16) char smem[];
    const uint32_t sb = smem_u32(smem);
    const int tid = threadIdx.x, wid = tid >> 5, lane = tid & 31;
    const int warpM = wid >> 2, warpN = wid & 3;
    const int b = blockIdx.y, m0 = blockIdx.x * 128;

    const __nv_bfloat16* Bb = Bk + (size_t)b * bstrideB;
    const int* kp = kidx + (size_t)b * kpitch;
    const int nch = (cnt[b] + 31) >> 5;

    float c[2][8][4];
#pragma unroll
    for (int i = 0; i < 2; i++)
#pragma unroll
        for (int j = 0; j < 8; j++)
#pragma unroll
            for (int r = 0; r < 4; r++) c[i][j][r] = 0.f;

    const int gr = tid >> 4;          // 0..31: gathered row within chunk
    const int aseg = tid & 15;        // A: 16 x 16B segments
    const int bsg = (tid & 15) * 2;   // B: 2 x 16B segments per thread

    auto load_stage = [&](int s, int cc) {
        uint32_t st = sb + s * STGC;
        const int* kc = kp + cc * 32;
        int k = __ldg(kc + gr);
        cpasync16(st + gr * APITCH + aseg * 16,
                  AT + (size_t)k * Mtot + m0 + aseg * 8);
        int kb = min(k, bclamp);
        const __nv_bfloat16* src = Bb + (size_t)kb * 256 + bsg * 8;
        cpasync16(st + ASTG + gr * BPITCH + bsg * 16, src);
        cpasync16(st + ASTG + gr * BPITCH + bsg * 16 + 16, src + 8);
        asm volatile("cp.async.commit_group;" ::: "memory");
    };

    if (nch > 0) {
        load_stage(0, 0);

        const int kr = (lane & 7) + ((lane >> 4) << 3);  // k-row within 16-blk
        const int ch8 = ((lane >> 3) & 1) << 3;          // +8 col for odd octet

        for (int cidx = 0; cidx < nch; cidx++) {
            int cur = cidx & 1;
            if (cidx + 1 < nch) {
                load_stage(cur ^ 1, cidx + 1);
                asm volatile("cp.async.wait_group 1;" ::: "memory");
            } else {
                asm volatile("cp.async.wait_group 0;" ::: "memory");
            }
            __syncthreads();

            uint32_t aBase = sb + cur * STGC;
            uint32_t bBase = aBase + ASTG;
#pragma unroll
            for (int ks = 0; ks < 2; ks++) {
                uint32_t arow = aBase + (uint32_t)(ks * 16 + kr) * APITCH;
                uint32_t brow = bBase + (uint32_t)(ks * 16 + kr) * BPITCH;
                uint32_t a0[4], a1[4];
                ldm4t(a0, arow + (uint32_t)(warpM * 32 + ch8) * 2);
                ldm4t(a1, arow + (uint32_t)(warpM * 32 + 16 + ch8) * 2);
#pragma unroll
                for (int gi = 0; gi < 4; gi++) {
                    uint32_t bb[4];
                    ldm4t(bb, brow + (uint32_t)(warpN * 64 + gi * 16 + ch8) * 2);
                    mma16816(c[0][gi * 2],     a0, bb[0], bb[2]);
                    mma16816(c[0][gi * 2 + 1], a0, bb[1], bb[3]);
                    mma16816(c[1][gi * 2],     a1, bb[0], bb[2]);
                    mma16816(c[1][gi * 2 + 1], a1, bb[1], bb[3]);
                }
            }
            __syncthreads();
        }
    }

    // ---- row sum-of-squares (deterministic order) ----
    float* sqsm = (float*)(smem + SQOFF);   // [4 warpN][128 rows]
    {
        float rs[2][2] = {{0.f, 0.f}, {0.f, 0.f}};
#pragma unroll
        for (int mi = 0; mi < 2; mi++)
#pragma unroll
            for (int nj = 0; nj < 8; nj++)
#pragma unroll
                for (int r = 0; r < 4; r++) {
                    float v = c[mi][nj][r];
                    rs[mi][r >> 1] += v * v;
                }
#pragma unroll
        for (int mi = 0; mi < 2; mi++)
#pragma unroll
            for (int h = 0; h < 2; h++) {
                float v = rs[mi][h];
                v += __shfl_xor_sync(0xffffffffu, v, 1);
                v += __shfl_xor_sync(0xffffffffu, v, 2);
                rs[mi][h] = v;
            }
        if ((lane & 3) == 0) {
#pragma unroll
            for (int mi = 0; mi < 2; mi++)
#pragma unroll
                for (int h = 0; h < 2; h++)
                    sqsm[warpN * 128 + warpM * 32 + mi * 16 + h * 8 + (lane >> 2)]
                        = rs[mi][h];
        }
    }
    __syncthreads();
    if (tid < 128) {
        float s = sqsm[tid] + sqsm[128 + tid] + sqsm[256 + tid] + sqsm[384 + tid];
        int mg = m0 + tid;
        g_dists[(size_t)b * NDIST + doff + mg] =
            fabsf(z[(size_t)b * Mtot + mg]) * rsqrtf(s);
    }

    // ---- V writeback (row-major C, layer 2 only) ----
    if (Vout) {
        __nv_bfloat16* Vb = Vout + (size_t)b * Mtot * 256;
#pragma unroll
        for (int mi = 0; mi < 2; mi++)
#pragma unroll
            for (int nj = 0; nj < 8; nj++)
#pragma unroll
                for (int rp = 0; rp < 2; rp++) {
                    int row = m0 + warpM * 32 + mi * 16 + rp * 8 + (lane >> 2);
                    int col = warpN * 64 + nj * 8 + (lane & 3) * 2;
                    __nv_bfloat162 p;
                    p.x = __float2bfloat16(c[mi][nj][rp * 2]);
                    p.y = __float2bfloat16(c[mi][nj][rp * 2 + 1]);
                    *(__nv_bfloat162*)(Vb + (size_t)row * 256 + col) = p;
                }
    }
}

// ---------------- per-batch smallest-k sum (dist1 computed inline) ---------
__global__ void topk_kernel(const float* __restrict__ z1)
{
    __shared__ float s[NDIST];
    __shared__ float rv[256];
    __shared__ int   ri[256];
    int b = blockIdx.x, t = threadIdx.x;
    for (int i = t; i < D1; i += 256)
        s[i] = fabsf(z1[(size_t)b * D1 + i]) * g_invn1[i];
    for (int i = D1 + t; i < NDIST; i += 256)
        s[i] = g_dists[b * NDIST + i];
    __syncthreads();
    float tot = 0.f;
    for (int it = 0; it < KSEL; it++) {
        float best = 3.402823466e38f; int bi = NDIST;
        for (int i = t; i < NDIST; i += 256) {
            float v = s[i];
            if (v < best) { best = v; bi = i; }
        }
        rv[t] = best; ri[t] = bi;
        __syncthreads();
        for (int st = 128; st > 0; st >>= 1) {
            if (t < st) {
                if (rv[t + st] < rv[t] ||
                    (rv[t + st] == rv[t] && ri[t + st] < ri[t])) {
                    rv[t] = rv[t + st]; ri[t] = ri[t + st];
                }
            }
            __syncthreads();
        }
        if (t == 0) { tot += rv[0]; s[ri[0]] = 3.402823466e38f; }
        __syncthreads();
    }
    if (t == 0) g_partial[b] = tot;
}

__global__ void final_reduce(float* __restrict__ out)
{
    __shared__ float sh[256];
    int t = threadIdx.x;
    sh[t] = g_partial[t];
    __syncthreads();
    for (int st = 128; st > 0; st >>= 1) {
        if (t < st) sh[t] += sh[t + st];
        __syncthreads();
    }
    if (t == 0) out[0] = sh[0];
}

// ---------------- launch -----------------------------------------------------
extern "C" void kernel_launch(void* const* d_in, const int* in_sizes, int n_in,
                              void* d_out, int out_size)
{
    const float* x  = (const float*)d_in[0];
    const float* W1 = (const float*)d_in[1];
    const float* b1 = (const float*)d_in[2];
    const float* W2 = (const float*)d_in[3];
    const float* b2 = (const float*)d_in[4];
    const float* W3 = (const float*)d_in[5];
    const float* b3 = (const float*)d_in[6];
    float* out = (float*)d_out;

    float *z1p, *h1p, *z2p, *h2p, *z3p;
    __nv_bfloat16 *w2t, *w3t, *w1b, *v2;
    int *ki1, *ci1, *ki2, *ci2;
    cudaGetSymbolAddress((void**)&z1p, g_z1);
    cudaGetSymbolAddress((void**)&h1p, g_h1);
    cudaGetSymbolAddress((void**)&z2p, g_z2);
    cudaGetSymbolAddress((void**)&h2p, g_h2);
    cudaGetSymbolAddress((void**)&z3p, g_z3);
    cudaGetSymbolAddress((void**)&w2t, g_W2T);
    cudaGetSymbolAddress((void**)&w3t, g_W3T);
    cudaGetSymbolAddress((void**)&w1b, g_W1b);
    cudaGetSymbolAddress((void**)&v2,  g_V2);
    cudaGetSymbolAddress((void**)&ki1, g_kidx1);
    cudaGetSymbolAddress((void**)&ci1, g_cnt1);
    cudaGetSymbolAddress((void**)&ki2, g_kidx2);
    cudaGetSymbolAddress((void**)&ci2, g_cnt2);

    cudaFuncSetAttribute(hmma_comp,
                         cudaFuncAttributeMaxDynamicSharedMemorySize, SMEMC);

    // #1: layer-1 forward  z1 = x @ W1^T + b1
    zgemm32<<<dim3(D1 / 64, B_ / 32), 256>>>(x, W1, b1, B_, D1, D_, z1p, h1p);
    // #2: fused compact(z1) + W2T/W1 casts + W1 norms
    compact1_prep<<<256 + 2050 + 1024 + 128, 256>>>(z1p, W1, W2);
    // #3: layer-2 forward  z2 = h1 @ W2^T + b2
    zgemm32<<<dim3(D2 / 64, B_ / 32), 256>>>(h1p, W2, b2, B_, D2, D1, z2p, h2p);
    // #4 (profiled): layer-2  V2[b] = (W2 o m1[b]) @ W1 -> dist2 + V2 bf16
    hmma_comp<<<dim3(D2 / 128, B_), 512, SMEMC>>>(
        w2t, w1b, (size_t)0, D1 - 1, ki1, ci1, D1 + 32,
        z2p, D2, D1, v2);
    // #5: layer-3 forward  z3 = h2 @ W3^T + b3
    zgemm32<<<dim3(D3 / 64, B_ / 32), 256>>>(h2p, W3, b3, B_, D3, D2, z3p, (float*)0);
    // #6: fused compact(z2) + W3T cast
    compact2_prep<<<256 + 513, 256>>>(z2p, W3);
    // #7: layer-3  V3[b] = (W3 o m2[b]) @ V2[b] -> dist3 only
    hmma_comp<<<dim3(D3 / 128, B_), 512, SMEMC>>>(
        w3t, v2, (size_t)D2 * D_, D2 - 1, ki2, ci2, D2 + 32,
        z3p, D3, D1 + D2, (__nv_bfloat16*)0);
    // #8, #9: smallest-10 per batch (dist1 inline), deterministic sum
    topk_kernel<<<B_, 256>>>(z1p);
    final_reduce<<<1, 256>>>(out);
}

// round 7
// speedup vs baseline: 6.4590x; 1.1144x over previous
#include <cuda_runtime.h>
#include <cuda_bf16.h>
#include <math.h>
#include <stdint.h>

// Problem dims (fixed by setup_inputs)
#define B_   256
#define D_   256
#define D1   1024
#define D2   512
#define D3   256
#define NDIST (D1 + D2 + D3)   // 1792
#define KSEL 10

// ---------------- scratch (device globals; no cudaMalloc allowed) ----------
__device__ float g_z1[B_ * D1];
__device__ float g_h1[B_ * D1];
__device__ float g_z2[B_ * D2];
__device__ float g_h2[B_ * D2];
__device__ float g_z3[B_ * D3];
__device__ __nv_bfloat16 g_W2T[(D1 + 1) * D2];            // [1025][512], row 1024 = 0
__device__ __nv_bfloat16 g_W3T[(D2 + 1) * D3];            // [513][256],  row 512  = 0
__device__ __nv_bfloat16 g_W1b[D1 * D_];                  // [1024][256]
__device__ __nv_bfloat16 g_V2[(size_t)B_ * D2 * D_];      // [B][512][256] row-major
__device__ int g_kidx1[B_ * (D1 + 32)];
__device__ int g_cnt1[B_];
__device__ int g_kidx2[B_ * (D2 + 32)];
__device__ int g_cnt2[B_];
__device__ float g_invn1[D1];
__device__ float g_dists[B_ * NDIST];
__device__ float g_partial[B_];

// ---------------- PTX helpers ------------------------------------------------
__device__ __forceinline__ uint32_t smem_u32(const void* p) {
    uint32_t a;
    asm("{ .reg .u64 t; cvta.to.shared.u64 t, %1; cvt.u32.u64 %0, t; }"
        : "=r"(a) : "l"(p));
    return a;
}
__device__ __forceinline__ void cpasync16(uint32_t dst, const void* src) {
    asm volatile("cp.async.cg.shared.global [%0], [%1], 16;"
                 :: "r"(dst), "l"(src) : "memory");
}
__device__ __forceinline__ void ldm4t(uint32_t r[4], uint32_t addr) {
    asm volatile("ldmatrix.sync.aligned.m8n8.x4.trans.shared.b16 {%0,%1,%2,%3}, [%4];"
                 : "=r"(r[0]), "=r"(r[1]), "=r"(r[2]), "=r"(r[3]) : "r"(addr));
}
__device__ __forceinline__ void mma16816(float* c, const uint32_t a[4],
                                         uint32_t b0, uint32_t b1) {
    asm volatile(
        "mma.sync.aligned.m16n8k16.row.col.f32.bf16.bf16.f32 "
        "{%0,%1,%2,%3}, {%4,%5,%6,%7}, {%8,%9}, {%0,%1,%2,%3};"
        : "+f"(c[0]), "+f"(c[1]), "+f"(c[2]), "+f"(c[3])
        : "r"(a[0]), "r"(a[1]), "r"(a[2]), "r"(a[3]), "r"(b0), "r"(b1));
}

// ---------------- forward-pass GEMM: Z = X @ W^T + bias --------------------
// BM=32, BN=64, BK=32; 256 threads; 2x4 per-thread microtile.
__global__ __launch_bounds__(256) void zgemm32(
    const float* __restrict__ X, const float* __restrict__ W,
    const float* __restrict__ bias, int M, int N, int K,
    float* __restrict__ Z, float* __restrict__ H)
{
    __shared__ __align__(16) float Xs[32][34];   // [k][m]
    __shared__ __align__(16) float Ws[32][68];   // [k][n]

    int m0 = blockIdx.y * 32, n0 = blockIdx.x * 64;
    int tid = threadIdx.x;
    int tx = tid & 15, ty = tid >> 4;
    int lrow = tid >> 3, lk = (tid & 7) * 4;

    float acc[2][4];
#pragma unroll
    for (int i = 0; i < 2; i++)
#pragma unroll
        for (int j = 0; j < 4; j++) acc[i][j] = 0.f;

    for (int k0 = 0; k0 < K; k0 += 32) {
        float4 xa = *(const float4*)(X + (size_t)(m0 + lrow) * K + k0 + lk);
        float4 w0 = *(const float4*)(W + (size_t)(n0 + lrow) * K + k0 + lk);
        float4 w1 = *(const float4*)(W + (size_t)(n0 + lrow + 32) * K + k0 + lk);
        __syncthreads();
        Xs[lk + 0][lrow] = xa.x; Xs[lk + 1][lrow] = xa.y;
        Xs[lk + 2][lrow] = xa.z; Xs[lk + 3][lrow] = xa.w;
        Ws[lk + 0][lrow] = w0.x; Ws[lk + 1][lrow] = w0.y;
        Ws[lk + 2][lrow] = w0.z; Ws[lk + 3][lrow] = w0.w;
        Ws[lk + 0][lrow + 32] = w1.x; Ws[lk + 1][lrow + 32] = w1.y;
        Ws[lk + 2][lrow + 32] = w1.z; Ws[lk + 3][lrow + 32] = w1.w;
        __syncthreads();
#pragma unroll
        for (int k = 0; k < 32; k++) {
            float a0 = Xs[k][ty * 2], a1 = Xs[k][ty * 2 + 1];
            float4 wv = *(float4*)&Ws[k][tx * 4];
            acc[0][0] += a0 * wv.x; acc[0][1] += a0 * wv.y;
            acc[0][2] += a0 * wv.z; acc[0][3] += a0 * wv.w;
            acc[1][0] += a1 * wv.x; acc[1][1] += a1 * wv.y;
            acc[1][2] += a1 * wv.z; acc[1][3] += a1 * wv.w;
        }
    }

#pragma unroll
    for (int i = 0; i < 2; i++) {
        int m = m0 + ty * 2 + i;
#pragma unroll
        for (int j = 0; j < 4; j++) {
            int n = n0 + tx * 4 + j;
            float zv = acc[i][j] + bias[n];
            size_t o = (size_t)m * N + n;
            Z[o] = zv;
            if (H) H[o] = zv > 0.f ? zv : 0.f;
        }
    }
}

// ---------------- deterministic per-batch active-k compaction (device fn) --
template <int KN>
__device__ __forceinline__ void compact_body(
    const float* __restrict__ z, int* __restrict__ kidx, int* __restrict__ cnt,
    int b, int t)
{
    const int E = KN / 256;
    const int kpitch = KN + 32;
    __shared__ int sh[256];
    int flag[E];
    int c = 0;
#pragma unroll
    for (int e = 0; e < E; e++) {
        flag[e] = (z[(size_t)b * KN + t * E + e] > 0.f) ? 1 : 0;
        c += flag[e];
    }
    sh[t] = c;
    __syncthreads();
    for (int s = 1; s < 256; s <<= 1) {
        int x = (t >= s) ? sh[t - s] : 0;
        __syncthreads();
        sh[t] += x;
        __syncthreads();
    }
    int pos = sh[t] - c;
#pragma unroll
    for (int e = 0; e < E; e++)
        if (flag[e]) kidx[(size_t)b * kpitch + pos++] = t * E + e;
    int total = sh[255];
    int padded = (total + 31) & ~31;
    int ip = total + t;
    if (ip < padded) kidx[(size_t)b * kpitch + ip] = KN;  // -> zero row of A^T
    if (t == 0) cnt[b] = total;
}

// fused: compact(z1) + W2T cast + W1 cast + W1 row inv-norms
__global__ void compact1_prep(const float* __restrict__ z1,
                              const float* __restrict__ W1,
                              const float* __restrict__ W2)
{
    int blk = blockIdx.x, t = threadIdx.x;
    if (blk < 256) {
        compact_body<D1>(z1, g_kidx1, g_cnt1, blk, t);
    } else if (blk < 256 + 2050) {
        int i = (blk - 256) * 256 + t;
        if (i < (D1 + 1) * D2) {
            int k = i >> 9, m = i & 511;
            g_W2T[i] = (k < D1) ? __float2bfloat16(W2[(size_t)m * D1 + k])
                                : __float2bfloat16(0.f);
        }
    } else if (blk < 256 + 2050 + 1024) {
        int i = (blk - 256 - 2050) * 256 + t;
        g_W1b[i] = __float2bfloat16(W1[i]);
    } else {
        int warp = (blk - 256 - 2050 - 1024) * 8 + (t >> 5);
        int lane = t & 31;
        const float4* vp = (const float4*)(W1 + (size_t)warp * D_);
        float4 v0 = vp[lane * 2], v1 = vp[lane * 2 + 1];
        float s = v0.x * v0.x + v0.y * v0.y + v0.z * v0.z + v0.w * v0.w
                + v1.x * v1.x + v1.y * v1.y + v1.z * v1.z + v1.w * v1.w;
#pragma unroll
        for (int o = 16; o; o >>= 1) s += __shfl_xor_sync(0xffffffffu, s, o);
        if (lane == 0) g_invn1[warp] = rsqrtf(s);
    }
}

// fused: compact(z2) + W3T cast.  grid = 256 + 513
__global__ void compact2_prep(const float* __restrict__ z2,
                              const float* __restrict__ W3)
{
    int blk = blockIdx.x, t = threadIdx.x;
    if (blk < 256) {
        compact_body<D2>(z2, g_kidx2, g_cnt2, blk, t);
    } else {
        int i = (blk - 256) * 256 + t;
        if (i < (D2 + 1) * D3) {
            int k = i >> 8, m = i & 255;
            g_W3T[i] = (k < D2) ? __float2bfloat16(W3[(size_t)m * D2 + k])
                                : __float2bfloat16(0.f);
        }
    }
}

// ---------------- HMMA k-compacted batched GEMM + fused epilogue ------------
// C[b] (128m x 256n fp32) = sum_{k in kidx[b]} AT[k][m] * Bk[b][k][n]
// 4-stage cp.async ring, ONE __syncthreads per chunk, 2-chunk-deep prefetch.
#define APITCH 272               // 32k x 128m bf16 rows padded to 272B
#define BPITCH 528               // 32k x 256n bf16 rows padded to 528B
#define ASTG   (32 * APITCH)     // 8704
#define BSTG   (32 * BPITCH)     // 16896
#define STGC   (ASTG + BSTG)     // 25600
#define NSTG   4
#define SQOFF  (NSTG * STGC)     // 102400
#define SMEMC  (SQOFF + 2048)

__global__ __launch_bounds__(512, 1) void hmma_comp(
    const __nv_bfloat16* __restrict__ AT, const __nv_bfloat16* __restrict__ Bk,
    size_t bstrideB, int bclamp,
    const int* __restrict__ kidx, const int* __restrict__ cnt, int kpitch,
    const float* __restrict__ z, int Mtot, int doff,
    __nv_bfloat16* __restrict__ Vout)
{
    extern __shared__ __align__(16) char smem[];
    const uint32_t sb = smem_u32(smem);
    const int tid = threadIdx.x, wid = tid >> 5, lane = tid & 31;
    const int warpM = wid >> 2, warpN = wid & 3;
    const int b = blockIdx.y, m0 = blockIdx.x * 128;

    const __nv_bfloat16* Bb = Bk + (size_t)b * bstrideB;
    const int* kp = kidx + (size_t)b * kpitch;
    const int nch = (cnt[b] + 31) >> 5;

    float c[2][8][4];
#pragma unroll
    for (int i = 0; i < 2; i++)
#pragma unroll
        for (int j = 0; j < 8; j++)
#pragma unroll
            for (int r = 0; r < 4; r++) c[i][j][r] = 0.f;

    const int gr = tid >> 4;          // 0..31: gathered row within chunk
    const int aseg = tid & 15;        // A: 16 x 16B segments
    const int bsg = (tid & 15) * 2;   // B: 2 x 16B segments per thread

    // issue loads for chunk cc into stage s; always commits a group
    auto load_stage = [&](int s, int cc) {
        if (cc < nch) {
            uint32_t st = sb + s * STGC;
            int k = __ldg(kp + cc * 32 + gr);
            cpasync16(st + gr * APITCH + aseg * 16,
                      AT + (size_t)k * Mtot + m0 + aseg * 8);
            int kb = min(k, bclamp);
            const __nv_bfloat16* src = Bb + (size_t)kb * 256 + bsg * 8;
            cpasync16(st + ASTG + gr * BPITCH + bsg * 16, src);
            cpasync16(st + ASTG + gr * BPITCH + bsg * 16 + 16, src + 8);
        }
        asm volatile("cp.async.commit_group;" ::: "memory");
    };

    if (nch > 0) {
        load_stage(0, 0);
        load_stage(1, 1);

        const int kr = (lane & 7) + ((lane >> 4) << 3);  // k-row within 16-blk
        const int ch8 = ((lane >> 3) & 1) << 3;          // +8 col for odd octet

        for (int cidx = 0; cidx < nch; cidx++) {
            int cur = cidx & (NSTG - 1);
            // chunk cidx resident (one group may still be pending)
            asm volatile("cp.async.wait_group 1;" ::: "memory");
            __syncthreads();
            // all warps finished chunk cidx-1 -> stage (cidx+2)&3 is free
            load_stage((cidx + 2) & (NSTG - 1), cidx + 2);

            uint32_t aBase = sb + cur * STGC;
            uint32_t bBase = aBase + ASTG;
#pragma unroll
            for (int ks = 0; ks < 2; ks++) {
                uint32_t arow = aBase + (uint32_t)(ks * 16 + kr) * APITCH;
                uint32_t brow = bBase + (uint32_t)(ks * 16 + kr) * BPITCH;
                uint32_t a0[4], a1[4];
                ldm4t(a0, arow + (uint32_t)(warpM * 32 + ch8) * 2);
                ldm4t(a1, arow + (uint32_t)(warpM * 32 + 16 + ch8) * 2);
#pragma unroll
                for (int gi = 0; gi < 4; gi++) {
                    uint32_t bb[4];
                    ldm4t(bb, brow + (uint32_t)(warpN * 64 + gi * 16 + ch8) * 2);
                    mma16816(c[0][gi * 2],     a0, bb[0], bb[2]);
                    mma16816(c[0][gi * 2 + 1], a0, bb[1], bb[3]);
                    mma16816(c[1][gi * 2],     a1, bb[0], bb[2]);
                    mma16816(c[1][gi * 2 + 1], a1, bb[1], bb[3]);
                }
            }
        }
        // drain remaining (empty) groups before smem reuse below
        asm volatile("cp.async.wait_group 0;" ::: "memory");
        __syncthreads();
    }

    // ---- row sum-of-squares (deterministic order) ----
    float* sqsm = (float*)(smem + SQOFF);   // [4 warpN][128 rows]
    {
        float rs[2][2] = {{0.f, 0.f}, {0.f, 0.f}};
#pragma unroll
        for (int mi = 0; mi < 2; mi++)
#pragma unroll
            for (int nj = 0; nj < 8; nj++)
#pragma unroll
                for (int r = 0; r < 4; r++) {
                    float v = c[mi][nj][r];
                    rs[mi][r >> 1] += v * v;
                }
#pragma unroll
        for (int mi = 0; mi < 2; mi++)
#pragma unroll
            for (int h = 0; h < 2; h++) {
                float v = rs[mi][h];
                v += __shfl_xor_sync(0xffffffffu, v, 1);
                v += __shfl_xor_sync(0xffffffffu, v, 2);
                rs[mi][h] = v;
            }
        if ((lane & 3) == 0) {
#pragma unroll
            for (int mi = 0; mi < 2; mi++)
#pragma unroll
                for (int h = 0; h < 2; h++)
                    sqsm[warpN * 128 + warpM * 32 + mi * 16 + h * 8 + (lane >> 2)]
                        = rs[mi][h];
        }
    }
    __syncthreads();
    if (tid < 128) {
        float s = sqsm[tid] + sqsm[128 + tid] + sqsm[256 + tid] + sqsm[384 + tid];
        int mg = m0 + tid;
        g_dists[(size_t)b * NDIST + doff + mg] =
            fabsf(z[(size_t)b * Mtot + mg]) * rsqrtf(s);
    }

    // ---- V writeback (row-major C, layer 2 only) ----
    if (Vout) {
        __nv_bfloat16* Vb = Vout + (size_t)b * Mtot * 256;
#pragma unroll
        for (int mi = 0; mi < 2; mi++)
#pragma unroll
            for (int nj = 0; nj < 8; nj++)
#pragma unroll
                for (int rp = 0; rp < 2; rp++) {
                    int row = m0 + warpM * 32 + mi * 16 + rp * 8 + (lane >> 2);
                    int col = warpN * 64 + nj * 8 + (lane & 3) * 2;
                    __nv_bfloat162 p;
                    p.x = __float2bfloat16(c[mi][nj][rp * 2]);
                    p.y = __float2bfloat16(c[mi][nj][rp * 2 + 1]);
                    *(__nv_bfloat162*)(Vb + (size_t)row * 256 + col) = p;
                }
    }
}

// ---------------- per-batch smallest-k sum (dist1 computed inline) ---------
__global__ void topk_kernel(const float* __restrict__ z1)
{
    __shared__ float s[NDIST];
    __shared__ float rv[256];
    __shared__ int   ri[256];
    int b = blockIdx.x, t = threadIdx.x;
    for (int i = t; i < D1; i += 256)
        s[i] = fabsf(z1[(size_t)b * D1 + i]) * g_invn1[i];
    for (int i = D1 + t; i < NDIST; i += 256)
        s[i] = g_dists[b * NDIST + i];
    __syncthreads();
    float tot = 0.f;
    for (int it = 0; it < KSEL; it++) {
        float best = 3.402823466e38f; int bi = NDIST;
        for (int i = t; i < NDIST; i += 256) {
            float v = s[i];
            if (v < best) { best = v; bi = i; }
        }
        rv[t] = best; ri[t] = bi;
        __syncthreads();
        for (int st = 128; st > 0; st >>= 1) {
            if (t < st) {
                if (rv[t + st] < rv[t] ||
                    (rv[t + st] == rv[t] && ri[t + st] < ri[t])) {
                    rv[t] = rv[t + st]; ri[t] = ri[t + st];
                }
            }
            __syncthreads();
        }
        if (t == 0) { tot += rv[0]; s[ri[0]] = 3.402823466e38f; }
        __syncthreads();
    }
    if (t == 0) g_partial[b] = tot;
}

__global__ void final_reduce(float* __restrict__ out)
{
    __shared__ float sh[256];
    int t = threadIdx.x;
    sh[t] = g_partial[t];
    __syncthreads();
    for (int st = 128; st > 0; st >>= 1) {
        if (t < st) sh[t] += sh[t + st];
        __syncthreads();
    }
    if (t == 0) out[0] = sh[0];
}

// ---------------- launch -----------------------------------------------------
extern "C" void kernel_launch(void* const* d_in, const int* in_sizes, int n_in,
                              void* d_out, int out_size)
{
    const float* x  = (const float*)d_in[0];
    const float* W1 = (const float*)d_in[1];
    const float* b1 = (const float*)d_in[2];
    const float* W2 = (const float*)d_in[3];
    const float* b2 = (const float*)d_in[4];
    const float* W3 = (const float*)d_in[5];
    const float* b3 = (const float*)d_in[6];
    float* out = (float*)d_out;

    float *z1p, *h1p, *z2p, *h2p, *z3p;
    __nv_bfloat16 *w2t, *w3t, *w1b, *v2;
    int *ki1, *ci1, *ki2, *ci2;
    cudaGetSymbolAddress((void**)&z1p, g_z1);
    cudaGetSymbolAddress((void**)&h1p, g_h1);
    cudaGetSymbolAddress((void**)&z2p, g_z2);
    cudaGetSymbolAddress((void**)&h2p, g_h2);
    cudaGetSymbolAddress((void**)&z3p, g_z3);
    cudaGetSymbolAddress((void**)&w2t, g_W2T);
    cudaGetSymbolAddress((void**)&w3t, g_W3T);
    cudaGetSymbolAddress((void**)&w1b, g_W1b);
    cudaGetSymbolAddress((void**)&v2,  g_V2);
    cudaGetSymbolAddress((void**)&ki1, g_kidx1);
    cudaGetSymbolAddress((void**)&ci1, g_cnt1);
    cudaGetSymbolAddress((void**)&ki2, g_kidx2);
    cudaGetSymbolAddress((void**)&ci2, g_cnt2);

    cudaFuncSetAttribute(hmma_comp,
                         cudaFuncAttributeMaxDynamicSharedMemorySize, SMEMC);

    // #1: layer-1 forward  z1 = x @ W1^T + b1
    zgemm32<<<dim3(D1 / 64, B_ / 32), 256>>>(x, W1, b1, B_, D1, D_, z1p, h1p);
    // #2: fused compact(z1) + W2T/W1 casts + W1 norms
    compact1_prep<<<256 + 2050 + 1024 + 128, 256>>>(z1p, W1, W2);
    // #3: layer-2 forward  z2 = h1 @ W2^T + b2
    zgemm32<<<dim3(D2 / 64, B_ / 32), 256>>>(h1p, W2, b2, B_, D2, D1, z2p, h2p);
    // #4 (profiled): layer-2  V2[b] = (W2 o m1[b]) @ W1 -> dist2 + V2 bf16
    hmma_comp<<<dim3(D2 / 128, B_), 512, SMEMC>>>(
        w2t, w1b, (size_t)0, D1 - 1, ki1, ci1, D1 + 32,
        z2p, D2, D1, v2);
    // #5: layer-3 forward  z3 = h2 @ W3^T + b3
    zgemm32<<<dim3(D3 / 64, B_ / 32), 256>>>(h2p, W3, b3, B_, D3, D2, z3p, (float*)0);
    // #6: fused compact(z2) + W3T cast
    compact2_prep<<<256 + 513, 256>>>(z2p, W3);
    // #7: layer-3  V3[b] = (W3 o m2[b]) @ V2[b] -> dist3 only
    hmma_comp<<<dim3(D3 / 128, B_), 512, SMEMC>>>(
        w3t, v2, (size_t)D2 * D_, D2 - 1, ki2, ci2, D2 + 32,
        z3p, D3, D1 + D2, (__nv_bfloat16*)0);
    // #8, #9: smallest-10 per batch (dist1 inline), deterministic sum
    topk_kernel<<<B_, 256>>>(z1p);
    final_reduce<<<1, 256>>>(out);
}

// round 8
// speedup vs baseline: 6.5952x; 1.0211x over previous
#include <cuda_runtime.h>
#include <cuda_bf16.h>
#include <math.h>
#include <stdint.h>

// Problem dims (fixed by setup_inputs)
#define B_   256
#define D_   256
#define D1   1024
#define D2   512
#define D3   256
#define NDIST (D1 + D2 + D3)   // 1792
#define KSEL 10

// ---------------- scratch (device globals; no cudaMalloc allowed) ----------
__device__ float g_z1[B_ * D1];
__device__ float g_h1[B_ * D1];
__device__ float g_z2[B_ * D2];
__device__ float g_h2[B_ * D2];
__device__ float g_z3[B_ * D3];
__device__ __nv_bfloat16 g_W2T[(D1 + 1) * D2];            // [1025][512], row 1024 = 0
__device__ __nv_bfloat16 g_W3T[(D2 + 1) * D3];            // [513][256],  row 512  = 0
__device__ __nv_bfloat16 g_W1b[D1 * D_];                  // [1024][256]
__device__ __nv_bfloat16 g_V2[(size_t)B_ * D2 * D_];      // [B][512][256] row-major
__device__ int g_kidx1[B_ * (D1 + 32)];
__device__ int g_cnt1[B_];
__device__ int g_kidx2[B_ * (D2 + 32)];
__device__ int g_cnt2[B_];
__device__ float g_invn1[D1];
__device__ float g_sqp2[2 * B_ * D2];                     // [ntile][b][m]
__device__ float g_sqp3[2 * B_ * D3];
__device__ float g_partial[B_];

// ---------------- PTX helpers ------------------------------------------------
__device__ __forceinline__ uint32_t smem_u32(const void* p) {
    uint32_t a;
    asm("{ .reg .u64 t; cvta.to.shared.u64 t, %1; cvt.u32.u64 %0, t; }"
        : "=r"(a) : "l"(p));
    return a;
}
__device__ __forceinline__ void cpasync16(uint32_t dst, const void* src) {
    asm volatile("cp.async.cg.shared.global [%0], [%1], 16;"
                 :: "r"(dst), "l"(src) : "memory");
}
__device__ __forceinline__ void ldm4t(uint32_t r[4], uint32_t addr) {
    asm volatile("ldmatrix.sync.aligned.m8n8.x4.trans.shared.b16 {%0,%1,%2,%3}, [%4];"
                 : "=r"(r[0]), "=r"(r[1]), "=r"(r[2]), "=r"(r[3]) : "r"(addr));
}
__device__ __forceinline__ void mma16816(float* c, const uint32_t a[4],
                                         uint32_t b0, uint32_t b1) {
    asm volatile(
        "mma.sync.aligned.m16n8k16.row.col.f32.bf16.bf16.f32 "
        "{%0,%1,%2,%3}, {%4,%5,%6,%7}, {%8,%9}, {%0,%1,%2,%3};"
        : "+f"(c[0]), "+f"(c[1]), "+f"(c[2]), "+f"(c[3])
        : "r"(a[0]), "r"(a[1]), "r"(a[2]), "r"(a[3]), "r"(b0), "r"(b1));
}

// ---------------- forward-pass GEMM: Z = X @ W^T + bias --------------------
__global__ __launch_bounds__(256) void zgemm32(
    const float* __restrict__ X, const float* __restrict__ W,
    const float* __restrict__ bias, int M, int N, int K,
    float* __restrict__ Z, float* __restrict__ H)
{
    __shared__ __align__(16) float Xs[32][34];   // [k][m]
    __shared__ __align__(16) float Ws[32][68];   // [k][n]

    int m0 = blockIdx.y * 32, n0 = blockIdx.x * 64;
    int tid = threadIdx.x;
    int tx = tid & 15, ty = tid >> 4;
    int lrow = tid >> 3, lk = (tid & 7) * 4;

    float acc[2][4];
#pragma unroll
    for (int i = 0; i < 2; i++)
#pragma unroll
        for (int j = 0; j < 4; j++) acc[i][j] = 0.f;

    for (int k0 = 0; k0 < K; k0 += 32) {
        float4 xa = *(const float4*)(X + (size_t)(m0 + lrow) * K + k0 + lk);
        float4 w0 = *(const float4*)(W + (size_t)(n0 + lrow) * K + k0 + lk);
        float4 w1 = *(const float4*)(W + (size_t)(n0 + lrow + 32) * K + k0 + lk);
        __syncthreads();
        Xs[lk + 0][lrow] = xa.x; Xs[lk + 1][lrow] = xa.y;
        Xs[lk + 2][lrow] = xa.z; Xs[lk + 3][lrow] = xa.w;
        Ws[lk + 0][lrow] = w0.x; Ws[lk + 1][lrow] = w0.y;
        Ws[lk + 2][lrow] = w0.z; Ws[lk + 3][lrow] = w0.w;
        Ws[lk + 0][lrow + 32] = w1.x; Ws[lk + 1][lrow + 32] = w1.y;
        Ws[lk + 2][lrow + 32] = w1.z; Ws[lk + 3][lrow + 32] = w1.w;
        __syncthreads();
#pragma unroll
        for (int k = 0; k < 32; k++) {
            float a0 = Xs[k][ty * 2], a1 = Xs[k][ty * 2 + 1];
            float4 wv = *(float4*)&Ws[k][tx * 4];
            acc[0][0] += a0 * wv.x; acc[0][1] += a0 * wv.y;
            acc[0][2] += a0 * wv.z; acc[0][3] += a0 * wv.w;
            acc[1][0] += a1 * wv.x; acc[1][1] += a1 * wv.y;
            acc[1][2] += a1 * wv.z; acc[1][3] += a1 * wv.w;
        }
    }

#pragma unroll
    for (int i = 0; i < 2; i++) {
        int m = m0 + ty * 2 + i;
#pragma unroll
        for (int j = 0; j < 4; j++) {
            int n = n0 + tx * 4 + j;
            float zv = acc[i][j] + bias[n];
            size_t o = (size_t)m * N + n;
            Z[o] = zv;
            if (H) H[o] = zv > 0.f ? zv : 0.f;
        }
    }
}

// ---------------- deterministic per-batch active-k compaction (device fn) --
template <int KN>
__device__ __forceinline__ void compact_body(
    const float* __restrict__ z, int* __restrict__ kidx, int* __restrict__ cnt,
    int b, int t)
{
    const int E = KN / 256;
    const int kpitch = KN + 32;
    __shared__ int sh[256];
    int flag[E];
    int c = 0;
#pragma unroll
    for (int e = 0; e < E; e++) {
        flag[e] = (z[(size_t)b * KN + t * E + e] > 0.f) ? 1 : 0;
        c += flag[e];
    }
    sh[t] = c;
    __syncthreads();
    for (int s = 1; s < 256; s <<= 1) {
        int x = (t >= s) ? sh[t - s] : 0;
        __syncthreads();
        sh[t] += x;
        __syncthreads();
    }
    int pos = sh[t] - c;
#pragma unroll
    for (int e = 0; e < E; e++)
        if (flag[e]) kidx[(size_t)b * kpitch + pos++] = t * E + e;
    int total = sh[255];
    int padded = (total + 31) & ~31;
    int ip = total + t;
    if (ip < padded) kidx[(size_t)b * kpitch + ip] = KN;  // -> zero row of A^T
    if (t == 0) cnt[b] = total;
}

// fused: compact(z1) + W2T cast + W1 cast + W1 row inv-norms
__global__ void compact1_prep(const float* __restrict__ z1,
                              const float* __restrict__ W1,
                              const float* __restrict__ W2)
{
    int blk = blockIdx.x, t = threadIdx.x;
    if (blk < 256) {
        compact_body<D1>(z1, g_kidx1, g_cnt1, blk, t);
    } else if (blk < 256 + 2050) {
        int i = (blk - 256) * 256 + t;
        if (i < (D1 + 1) * D2) {
            int k = i >> 9, m = i & 511;
            g_W2T[i] = (k < D1) ? __float2bfloat16(W2[(size_t)m * D1 + k])
                                : __float2bfloat16(0.f);
        }
    } else if (blk < 256 + 2050 + 1024) {
        int i = (blk - 256 - 2050) * 256 + t;
        g_W1b[i] = __float2bfloat16(W1[i]);
    } else {
        int warp = (blk - 256 - 2050 - 1024) * 8 + (t >> 5);
        int lane = t & 31;
        const float4* vp = (const float4*)(W1 + (size_t)warp * D_);
        float4 v0 = vp[lane * 2], v1 = vp[lane * 2 + 1];
        float s = v0.x * v0.x + v0.y * v0.y + v0.z * v0.z + v0.w * v0.w
                + v1.x * v1.x + v1.y * v1.y + v1.z * v1.z + v1.w * v1.w;
#pragma unroll
        for (int o = 16; o; o >>= 1) s += __shfl_xor_sync(0xffffffffu, s, o);
        if (lane == 0) g_invn1[warp] = rsqrtf(s);
    }
}

// fused: compact(z2) + W3T cast.  grid = 256 + 513
__global__ void compact2_prep(const float* __restrict__ z2,
                              const float* __restrict__ W3)
{
    int blk = blockIdx.x, t = threadIdx.x;
    if (blk < 256) {
        compact_body<D2>(z2, g_kidx2, g_cnt2, blk, t);
    } else {
        int i = (blk - 256) * 256 + t;
        if (i < (D2 + 1) * D3) {
            int k = i >> 8, m = i & 255;
            g_W3T[i] = (k < D2) ? __float2bfloat16(W3[(size_t)m * D2 + k])
                                : __float2bfloat16(0.f);
        }
    }
}

// ---------------- HMMA k-compacted batched GEMM (128x128 tile) --------------
// grid (Mtot/128, 2 ntiles, B_); 256 threads; 2 CTAs/SM.
// C = sum_{k in kidx[b]} AT[k][m0+..] * Bk[b][k][n0+..]
// Writes per-row partial sum-of-squares to sqout[ntile][b][m] and optional V.
#define APITCH 272               // 32k x 128m bf16 rows padded to 272B
#define BPITCH 272               // 32k x 128n bf16 rows padded to 272B
#define ASTG   (32 * APITCH)     // 8704
#define BSTG   (32 * BPITCH)     // 8704
#define STGC   (ASTG + BSTG)     // 17408
#define NSTG   3
#define SQOFF  (NSTG * STGC)     // 52224
#define SMEMC  (SQOFF + 1024)

__global__ __launch_bounds__(256, 2) void hmma_comp(
    const __nv_bfloat16* __restrict__ AT, const __nv_bfloat16* __restrict__ Bk,
    size_t bstrideB, int bclamp,
    const int* __restrict__ kidx, const int* __restrict__ cnt, int kpitch,
    int Mtot, float* __restrict__ sqout,
    __nv_bfloat16* __restrict__ Vout)
{
    extern __shared__ __align__(16) char smem[];
    const uint32_t sb = smem_u32(smem);
    const int tid = threadIdx.x, wid = tid >> 5, lane = tid & 31;
    const int warpM = wid >> 1, warpN = wid & 1;
    const int m0 = blockIdx.x * 128, n0 = blockIdx.y * 128;
    const int b = blockIdx.z;

    const __nv_bfloat16* Bb = Bk + (size_t)b * bstrideB;
    const int* kp = kidx + (size_t)b * kpitch;
    const int nch = (cnt[b] + 31) >> 5;

    float c[2][8][4];
#pragma unroll
    for (int i = 0; i < 2; i++)
#pragma unroll
        for (int j = 0; j < 8; j++)
#pragma unroll
            for (int r = 0; r < 4; r++) c[i][j][r] = 0.f;

    const int gr = tid >> 3;          // 0..31: gathered row within chunk
    const int sg = tid & 7;           // 8 threads per row; 2x16B segs each

    // issue loads for chunk cc into stage s; always commits a group
    auto load_stage = [&](int s, int cc) {
        if (cc < nch) {
            uint32_t st = sb + s * STGC;
            int k = __ldg(kp + cc * 32 + gr);
            const __nv_bfloat16* asrc = AT + (size_t)k * Mtot + m0 + sg * 16;
            cpasync16(st + gr * APITCH + sg * 32, asrc);
            cpasync16(st + gr * APITCH + sg * 32 + 16, asrc + 8);
            int kb = min(k, bclamp);
            const __nv_bfloat16* bsrc = Bb + (size_t)kb * 256 + n0 + sg * 16;
            cpasync16(st + ASTG + gr * BPITCH + sg * 32, bsrc);
            cpasync16(st + ASTG + gr * BPITCH + sg * 32 + 16, bsrc + 8);
        }
        asm volatile("cp.async.commit_group;" ::: "memory");
    };

    if (nch > 0) {
        load_stage(0, 0);
        load_stage(1, 1);

        const int kr = (lane & 7) + ((lane >> 4) << 3);  // k-row within 16-blk
        const int ch8 = ((lane >> 3) & 1) << 3;          // +8 col for odd octet

        for (int cidx = 0; cidx < nch; cidx++) {
            int cur = cidx % NSTG;
            asm volatile("cp.async.wait_group 1;" ::: "memory");
            __syncthreads();
            load_stage((cidx + 2) % NSTG, cidx + 2);

            uint32_t aBase = sb + cur * STGC;
            uint32_t bBase = aBase + ASTG;
#pragma unroll
            for (int ks = 0; ks < 2; ks++) {
                uint32_t arow = aBase + (uint32_t)(ks * 16 + kr) * APITCH;
                uint32_t brow = bBase + (uint32_t)(ks * 16 + kr) * BPITCH;
                uint32_t a0[4], a1[4];
                ldm4t(a0, arow + (uint32_t)(warpM * 32 + ch8) * 2);
                ldm4t(a1, arow + (uint32_t)(warpM * 32 + 16 + ch8) * 2);
#pragma unroll
                for (int gi = 0; gi < 4; gi++) {
                    uint32_t bb[4];
                    ldm4t(bb, brow + (uint32_t)(warpN * 64 + gi * 16 + ch8) * 2);
                    mma16816(c[0][gi * 2],     a0, bb[0], bb[2]);
                    mma16816(c[0][gi * 2 + 1], a0, bb[1], bb[3]);
                    mma16816(c[1][gi * 2],     a1, bb[0], bb[2]);
                    mma16816(c[1][gi * 2 + 1], a1, bb[1], bb[3]);
                }
            }
        }
        asm volatile("cp.async.wait_group 0;" ::: "memory");
        __syncthreads();
    }

    // ---- per-row partial sum-of-squares (deterministic order) ----
    float* sqsm = (float*)(smem + SQOFF);   // [2 warpN][128 rows]
    {
        float rs[2][2] = {{0.f, 0.f}, {0.f, 0.f}};
#pragma unroll
        for (int mi = 0; mi < 2; mi++)
#pragma unroll
            for (int nj = 0; nj < 8; nj++)
#pragma unroll
                for (int r = 0; r < 4; r++) {
                    float v = c[mi][nj][r];
                    rs[mi][r >> 1] += v * v;
                }
#pragma unroll
        for (int mi = 0; mi < 2; mi++)
#pragma unroll
            for (int h = 0; h < 2; h++) {
                float v = rs[mi][h];
                v += __shfl_xor_sync(0xffffffffu, v, 1);
                v += __shfl_xor_sync(0xffffffffu, v, 2);
                rs[mi][h] = v;
            }
        if ((lane & 3) == 0) {
#pragma unroll
            for (int mi = 0; mi < 2; mi++)
#pragma unroll
                for (int h = 0; h < 2; h++)
                    sqsm[warpN * 128 + warpM * 32 + mi * 16 + h * 8 + (lane >> 2)]
                        = rs[mi][h];
        }
    }
    __syncthreads();
    if (tid < 128) {
        float s = sqsm[tid] + sqsm[128 + tid];
        sqout[((size_t)blockIdx.y * B_ + b) * Mtot + m0 + tid] = s;
    }

    // ---- V writeback (row-major C, layer 2 only) ----
    if (Vout) {
        __nv_bfloat16* Vb = Vout + (size_t)b * Mtot * 256;
#pragma unroll
        for (int mi = 0; mi < 2; mi++)
#pragma unroll
            for (int nj = 0; nj < 8; nj++)
#pragma unroll
                for (int rp = 0; rp < 2; rp++) {
                    int row = m0 + warpM * 32 + mi * 16 + rp * 8 + (lane >> 2);
                    int col = n0 + warpN * 64 + nj * 8 + (lane & 3) * 2;
                    __nv_bfloat162 p;
                    p.x = __float2bfloat16(c[mi][nj][rp * 2]);
                    p.y = __float2bfloat16(c[mi][nj][rp * 2 + 1]);
                    *(__nv_bfloat162*)(Vb + (size_t)row * 256 + col) = p;
                }
    }
}

// ---------------- per-batch smallest-k sum (all dists computed inline) ------
__global__ void topk_kernel(const float* __restrict__ z1,
                            const float* __restrict__ z2,
                            const float* __restrict__ z3)
{
    __shared__ float s[NDIST];
    __shared__ float rv[256];
    __shared__ int   ri[256];
    int b = blockIdx.x, t = threadIdx.x;
    for (int i = t; i < D1; i += 256)
        s[i] = fabsf(z1[(size_t)b * D1 + i]) * g_invn1[i];
    for (int i = t; i < D2; i += 256) {
        float sq = g_sqp2[(size_t)b * D2 + i] + g_sqp2[(size_t)(B_ + b) * D2 + i];
        s[D1 + i] = fabsf(z2[(size_t)b * D2 + i]) * rsqrtf(sq);
    }
    if (t < D3) {
        float sq = g_sqp3[(size_t)b * D3 + t] + g_sqp3[(size_t)(B_ + b) * D3 + t];
        s[D1 + D2 + t] = fabsf(z3[(size_t)b * D3 + t]) * rsqrtf(sq);
    }
    __syncthreads();
    float tot = 0.f;
    for (int it = 0; it < KSEL; it++) {
        float best = 3.402823466e38f; int bi = NDIST;
        for (int i = t; i < NDIST; i += 256) {
            float v = s[i];
            if (v < best) { best = v; bi = i; }
        }
        rv[t] = best; ri[t] = bi;
        __syncthreads();
        for (int st = 128; st > 0; st >>= 1) {
            if (t < st) {
                if (rv[t + st] < rv[t] ||
                    (rv[t + st] == rv[t] && ri[t + st] < ri[t])) {
                    rv[t] = rv[t + st]; ri[t] = ri[t + st];
                }
            }
            __syncthreads();
        }
        if (t == 0) { tot += rv[0]; s[ri[0]] = 3.402823466e38f; }
        __syncthreads();
    }
    if (t == 0) g_partial[b] = tot;
}

__global__ void final_reduce(float* __restrict__ out)
{
    __shared__ float sh[256];
    int t = threadIdx.x;
    sh[t] = g_partial[t];
    __syncthreads();
    for (int st = 128; st > 0; st >>= 1) {
        if (t < st) sh[t] += sh[t + st];
        __syncthreads();
    }
    if (t == 0) out[0] = sh[0];
}

// ---------------- launch -----------------------------------------------------
extern "C" void kernel_launch(void* const* d_in, const int* in_sizes, int n_in,
                              void* d_out, int out_size)
{
    const float* x  = (const float*)d_in[0];
    const float* W1 = (const float*)d_in[1];
    const float* b1 = (const float*)d_in[2];
    const float* W2 = (const float*)d_in[3];
    const float* b2 = (const float*)d_in[4];
    const float* W3 = (const float*)d_in[5];
    const float* b3 = (const float*)d_in[6];
    float* out = (float*)d_out;

    float *z1p, *h1p, *z2p, *h2p, *z3p, *sq2p, *sq3p;
    __nv_bfloat16 *w2t, *w3t, *w1b, *v2;
    int *ki1, *ci1, *ki2, *ci2;
    cudaGetSymbolAddress((void**)&z1p, g_z1);
    cudaGetSymbolAddress((void**)&h1p, g_h1);
    cudaGetSymbolAddress((void**)&z2p, g_z2);
    cudaGetSymbolAddress((void**)&h2p, g_h2);
    cudaGetSymbolAddress((void**)&z3p, g_z3);
    cudaGetSymbolAddress((void**)&sq2p, g_sqp2);
    cudaGetSymbolAddress((void**)&sq3p, g_sqp3);
    cudaGetSymbolAddress((void**)&w2t, g_W2T);
    cudaGetSymbolAddress((void**)&w3t, g_W3T);
    cudaGetSymbolAddress((void**)&w1b, g_W1b);
    cudaGetSymbolAddress((void**)&v2,  g_V2);
    cudaGetSymbolAddress((void**)&ki1, g_kidx1);
    cudaGetSymbolAddress((void**)&ci1, g_cnt1);
    cudaGetSymbolAddress((void**)&ki2, g_kidx2);
    cudaGetSymbolAddress((void**)&ci2, g_cnt2);

    cudaFuncSetAttribute(hmma_comp,
                         cudaFuncAttributeMaxDynamicSharedMemorySize, SMEMC);

    // #1: layer-1 forward  z1 = x @ W1^T + b1
    zgemm32<<<dim3(D1 / 64, B_ / 32), 256>>>(x, W1, b1, B_, D1, D_, z1p, h1p);
    // #2: fused compact(z1) + W2T/W1 casts + W1 norms
    compact1_prep<<<256 + 2050 + 1024 + 128, 256>>>(z1p, W1, W2);
    // #3: layer-2 forward  z2 = h1 @ W2^T + b2
    zgemm32<<<dim3(D2 / 64, B_ / 32), 256>>>(h1p, W2, b2, B_, D2, D1, z2p, h2p);
    // #4 (profiled): layer-2  V2[b] = (W2 o m1[b]) @ W1 -> sq partials + V2
    hmma_comp<<<dim3(D2 / 128, 2, B_), 256, SMEMC>>>(
        w2t, w1b, (size_t)0, D1 - 1, ki1, ci1, D1 + 32,
        D2, sq2p, v2);
    // #5: layer-3 forward  z3 = h2 @ W3^T + b3
    zgemm32<<<dim3(D3 / 64, B_ / 32), 256>>>(h2p, W3, b3, B_, D3, D2, z3p, (float*)0);
    // #6: fused compact(z2) + W3T cast
    compact2_prep<<<256 + 513, 256>>>(z2p, W3);
    // #7: layer-3  V3[b] = (W3 o m2[b]) @ V2[b] -> sq partials only
    hmma_comp<<<dim3(D3 / 128, 2, B_), 256, SMEMC>>>(
        w3t, v2, (size_t)D2 * D_, D2 - 1, ki2, ci2, D2 + 32,
        D3, sq3p, (__nv_bfloat16*)0);
    // #8, #9: smallest-10 per batch (all dists inline), deterministic sum
    topk_kernel<<<B_, 256>>>(z1p, z2p, z3p);
    final_reduce<<<1, 256>>>(out);
}